// round 1
// baseline (speedup 1.0000x reference)
#include <cuda_runtime.h>

#define BB 16384
#define DD 256
#define KK 3000
#define NSLAB 64
#define SLABROWS (BB / NSLAB)   // 256

static __device__ __forceinline__ float INV_EPS_F() { return 20.0f; }  // 1/0.05
static __device__ __forceinline__ float INV_T_F()   { return 10.0f; }  // 1/0.1

// ---------------- scratch (static device globals; no runtime alloc) ---------
__device__ float g_nqk[(size_t)2 * BB * DD];   // normalized q (rows 0..B-1), k (rows B..2B-1)
__device__ float g_nc [(size_t)KK * DD];       // normalized cluster centers
__device__ float g_S  [(size_t)2 * BB * KK];   // stacked sims: rows 0..B-1 = nq@c^T, B..2B-1 = nk@c^T
__device__ float g_part[NSLAB * KK];           // column-sum slab partials
__device__ float g_W[KK];
__device__ float g_u[KK];
__device__ float g_logu[KK];
__device__ float g_v[BB];
__device__ float g_Z;
__device__ float g_rowloss[BB];
__device__ float g_loss[2];

// ---------------- reduction helpers (deterministic) --------------------------
__device__ __forceinline__ float blk_reduce_sum(float v, float* red) {
    int tid = threadIdx.x;
    red[tid] = v;
    __syncthreads();
    for (int s = blockDim.x >> 1; s > 0; s >>= 1) {
        if (tid < s) red[tid] += red[tid + s];
        __syncthreads();
    }
    float r = red[0];
    __syncthreads();
    return r;
}

__device__ __forceinline__ float blk_reduce_max(float v, float* red) {
    int tid = threadIdx.x;
    red[tid] = v;
    __syncthreads();
    for (int s = blockDim.x >> 1; s > 0; s >>= 1) {
        if (tid < s) red[tid] = fmaxf(red[tid], red[tid + s]);
        __syncthreads();
    }
    float r = red[0];
    __syncthreads();
    return r;
}

// ---------------- 1) row L2 normalize (one warp per row, D=256) --------------
__global__ void l2norm_kernel(const float* __restrict__ in, int rows, int dstSel) {
    float* outBase = (dstSel == 0) ? g_nqk
                   : (dstSel == 1) ? (g_nqk + (size_t)BB * DD)
                   : g_nc;
    int row  = blockIdx.x * (blockDim.x >> 5) + (threadIdx.x >> 5);
    int lane = threadIdx.x & 31;
    if (row >= rows) return;
    const float* p = in + (size_t)row * DD;
    float v[8];
    float s = 0.0f;
#pragma unroll
    for (int i = 0; i < 8; i++) { v[i] = p[lane + 32 * i]; s += v[i] * v[i]; }
#pragma unroll
    for (int o = 16; o > 0; o >>= 1) s += __shfl_xor_sync(0xffffffffu, s, o);
    float inv = 1.0f / fmaxf(sqrtf(s), 1e-12f);
    float* q = outBase + (size_t)row * DD;
#pragma unroll
    for (int i = 0; i < 8; i++) q[lane + 32 * i] = v[i] * inv;
}

// ---------------- 2) SGEMM: g_S[32768,3000] = g_nqk[32768,256] @ g_nc[3000,256]^T
// 128x128 block tile, K-chunk 16, 8x8 per thread, 256 threads.
__global__ void sgemm_nt_kernel() {
    constexpr int BMt = 128, BNt = 128, BKt = 16;
    __shared__ float As[BKt][BMt];
    __shared__ float Bs[BKt][BNt];
    const int tid = threadIdx.x;
    const int tx = tid & 15, ty = tid >> 4;
    const int mBase = blockIdx.y * BMt;
    const int nBase = blockIdx.x * BNt;

    float acc[8][8] = {};

    for (int k0 = 0; k0 < DD; k0 += BKt) {
#pragma unroll
        for (int i = 0; i < 2; i++) {
            int idx = tid + i * 256;
            int r = idx >> 2;
            int c = (idx & 3) << 2;
            const float4 va = *reinterpret_cast<const float4*>(
                &g_nqk[(size_t)(mBase + r) * DD + k0 + c]);
            As[c + 0][r] = va.x; As[c + 1][r] = va.y;
            As[c + 2][r] = va.z; As[c + 3][r] = va.w;
            int gn = nBase + r;
            float4 vb = make_float4(0.f, 0.f, 0.f, 0.f);
            if (gn < KK)
                vb = *reinterpret_cast<const float4*>(&g_nc[(size_t)gn * DD + k0 + c]);
            Bs[c + 0][r] = vb.x; Bs[c + 1][r] = vb.y;
            Bs[c + 2][r] = vb.z; Bs[c + 3][r] = vb.w;
        }
        __syncthreads();
#pragma unroll
        for (int kk = 0; kk < BKt; kk++) {
            float ra[8], rb[8];
#pragma unroll
            for (int i = 0; i < 8; i++) ra[i] = As[kk][ty * 8 + i];
#pragma unroll
            for (int j = 0; j < 8; j++) rb[j] = Bs[kk][tx * 8 + j];
#pragma unroll
            for (int i = 0; i < 8; i++)
#pragma unroll
                for (int j = 0; j < 8; j++)
                    acc[i][j] = fmaf(ra[i], rb[j], acc[i][j]);
        }
        __syncthreads();
    }

#pragma unroll
    for (int i = 0; i < 8; i++) {
        int gm = mBase + ty * 8 + i;
#pragma unroll
        for (int j = 0; j < 8; j += 4) {
            int gn = nBase + tx * 8 + j;
            if (gn + 3 < KK) {
                float4 o = make_float4(acc[i][j], acc[i][j + 1], acc[i][j + 2], acc[i][j + 3]);
                *reinterpret_cast<float4*>(&g_S[(size_t)gm * KK + gn]) = o;
            } else {
#pragma unroll
                for (int jj = 0; jj < 4; jj++)
                    if (gn + jj < KK) g_S[(size_t)gm * KK + gn + jj] = acc[i][jj + j];
            }
        }
    }
}

// ---------------- 3) column sums of E (optionally v-weighted), per slab ------
__global__ void colsum_kernel(int simRowOff, int useV) {
    int k = blockIdx.x * blockDim.x + threadIdx.x;
    if (k >= KK) return;
    int slab = blockIdx.y;
    int r0 = slab * SLABROWS;
    const float* p = g_S + (size_t)(simRowOff + r0) * KK + k;
    float acc = 0.0f;
    if (useV) {
        for (int r = 0; r < SLABROWS; r++)
            acc += g_v[r0 + r] * expf(p[(size_t)r * KK] * INV_EPS_F());
    } else {
        for (int r = 0; r < SLABROWS; r++)
            acc += expf(p[(size_t)r * KK] * INV_EPS_F());
    }
    g_part[slab * KK + k] = acc;
}

__global__ void reduce_w_kernel() {
    int k = blockIdx.x * blockDim.x + threadIdx.x;
    if (k >= KK) return;
    float s = 0.0f;
#pragma unroll 8
    for (int i = 0; i < NSLAB; i++) s += g_part[i * KK + k];
    g_W[k] = s;
}

__global__ void zreduce_kernel() {
    __shared__ float red[1024];
    float a = 0.0f;
    for (int k = threadIdx.x; k < KK; k += 1024) a += g_W[k];
    float z = blk_reduce_sum(a, red);
    if (threadIdx.x == 0) g_Z = z;
}

__global__ void compute_u_kernel() {
    int k = blockIdx.x * blockDim.x + threadIdx.x;
    if (k >= KK) return;
    float u = g_Z / ((float)KK * g_W[k]);
    g_u[k] = u;
    g_logu[k] = logf(u);
}

// ---------------- 4) row sums M_b (u-weighted), update v ---------------------
__global__ void rownorm_v_kernel(int simRowOff) {
    __shared__ float red[256];
    int b = blockIdx.x;
    const float* row = g_S + (size_t)(simRowOff + b) * KK;
    float acc = 0.0f;
    for (int k = threadIdx.x; k < KK; k += 256)
        acc += g_u[k] * expf(row[k] * INV_EPS_F());
    float m = blk_reduce_sum(acc, red);
    if (threadIdx.x == 0) g_v[b] = g_Z / ((float)BB * m);
}

// ---------------- 5) fused final: v3 + logsumexp(pred/T) + KL per row --------
__global__ void final_row_kernel(int simRowOff, int predRowOff) {
    __shared__ float ssim[KK];
    __shared__ float spred[KK];
    __shared__ float red[256];
    __shared__ float s_mb;
    int b = blockIdx.x, tid = threadIdx.x;
    const float* srow = g_S + (size_t)(simRowOff + b) * KK;
    const float* prow = g_S + (size_t)(predRowOff + b) * KK;
    for (int k = tid; k < KK; k += 256) { ssim[k] = srow[k]; spred[k] = prow[k]; }
    __syncthreads();

    // M_b with final u  (v3_b = Z/(B*M_b);  code = u_k*E/M_b)
    float acc = 0.0f;
    for (int k = tid; k < KK; k += 256)
        acc += g_u[k] * expf(ssim[k] * INV_EPS_F());
    float mb = blk_reduce_sum(acc, red);
    if (tid == 0) s_mb = mb;
    __syncthreads();
    mb = s_mb;

    // logsumexp over pred/T
    float mx = -1e30f;
    for (int k = tid; k < KK; k += 256)
        mx = fmaxf(mx, spred[k] * INV_T_F());
    float m = blk_reduce_max(mx, red);
    float se = 0.0f;
    for (int k = tid; k < KK; k += 256)
        se += expf(spred[k] * INV_T_F() - m);
    float ssum = blk_reduce_sum(se, red);
    float lse = m + logf(ssum);

    // KL accumulation: code = u_k*E/M_b ; log code = logu_k + sim/eps - log(M_b)
    float invMb = 1.0f / mb;
    float negLogMb = -logf(mb);
    float L = 0.0f;
    for (int k = tid; k < KK; k += 256) {
        float se2   = ssim[k] * INV_EPS_F();
        float e     = expf(se2);
        float code  = g_u[k] * e * invMb;
        float logc  = g_logu[k] + se2 + negLogMb;
        float logp  = spred[k] * INV_T_F() - lse;
        L += code * (logc - logp);
    }
    float Lb = blk_reduce_sum(L, red);
    if (tid == 0) g_rowloss[b] = Lb;
}

__global__ void loss_reduce_kernel(int lossIdx) {
    __shared__ float red[1024];
    float a = 0.0f;
    for (int b = threadIdx.x; b < BB; b += 1024) a += g_rowloss[b];
    float s = blk_reduce_sum(a, red);
    if (threadIdx.x == 0) g_loss[lossIdx] = s / (float)BB;
}

__global__ void combine_kernel(float* out) {
    out[0] = 0.5f * (g_loss[0] + g_loss[1]);
}

// ---------------- launch ------------------------------------------------------
extern "C" void kernel_launch(void* const* d_in, const int* in_sizes, int n_in,
                              void* d_out, int out_size) {
    const float* q = (const float*)d_in[0];
    const float* k = (const float*)d_in[1];
    const float* c = (const float*)d_in[2];

    // normalize (8 rows per 256-thread block; one warp per row)
    l2norm_kernel<<<BB / 8, 256>>>(q, BB, 0);
    l2norm_kernel<<<BB / 8, 256>>>(k, BB, 1);
    l2norm_kernel<<<(KK + 7) / 8, 256>>>(c, KK, 2);

    // stacked GEMM: [2B, D] x [K, D]^T -> [2B, K]
    dim3 gg((KK + 127) / 128, (2 * BB) / 128);
    sgemm_nt_kernel<<<gg, 256>>>();

    dim3 cg((KK + 127) / 128, NSLAB);
    for (int l = 0; l < 2; l++) {
        // loss1: sim = nk@c^T (rows B..2B-1), pred = nq@c^T (rows 0..B-1); loss2 swapped
        int simOff  = (l == 0) ? BB : 0;
        int predOff = (l == 0) ? 0 : BB;

        // --- sinkhorn iter 1 ---
        colsum_kernel<<<cg, 128>>>(simOff, 0);
        reduce_w_kernel<<<(KK + 127) / 128, 128>>>();
        zreduce_kernel<<<1, 1024>>>();
        compute_u_kernel<<<(KK + 127) / 128, 128>>>();
        rownorm_v_kernel<<<BB, 256>>>(simOff);
        // --- iter 2 ---
        colsum_kernel<<<cg, 128>>>(simOff, 1);
        reduce_w_kernel<<<(KK + 127) / 128, 128>>>();
        compute_u_kernel<<<(KK + 127) / 128, 128>>>();
        rownorm_v_kernel<<<BB, 256>>>(simOff);
        // --- iter 3 (v3 fused into final) ---
        colsum_kernel<<<cg, 128>>>(simOff, 1);
        reduce_w_kernel<<<(KK + 127) / 128, 128>>>();
        compute_u_kernel<<<(KK + 127) / 128, 128>>>();

        final_row_kernel<<<BB, 256>>>(simOff, predOff);
        loss_reduce_kernel<<<1, 1024>>>(l);
    }
    combine_kernel<<<1, 1>>>((float*)d_out);
}

// round 4
// speedup vs baseline: 1.2146x; 1.2146x over previous
#include <cuda_runtime.h>
#include <cuda_bf16.h>
#include <cstdint>

#define BB 16384
#define DD 256
#define KK 3000
#define KPAD 3072
#define K3 768           // hi|mid|lo concatenated K
#define NSLAB 64
#define SLABROWS 256

#define C_EXP20 28.853900817779268f   // 20/ln2
#define C_EXP10 14.426950408889634f   // 10/ln2
#define C_LN2   0.6931471805599453f

// ---------------- device scratch -------------------------------------------
__device__ __align__(16) __nv_bfloat16 g_A2[(size_t)2 * BB * K3];   // [hi|mid|lo] per row
__device__ __align__(16) __nv_bfloat16 g_B2[(size_t)KPAD * K3];
__device__ float g_S[(size_t)2 * BB * KK];   // rows 0..B-1 = nq@c^T ; B..2B-1 = nk@c^T
__device__ float g_E[(size_t)BB * KK];
__device__ float g_part[NSLAB * KK];
__device__ float g_W[KK];
__device__ float g_u[KK];
__device__ float g_logu[KK];
__device__ float g_v[BB];
__device__ float g_Z;
__device__ float g_rowloss[BB];
__device__ float g_loss[2];

// ---------------- helpers ----------------------------------------------------
static __device__ __forceinline__ float ex2f(float x) {
    float y; asm("ex2.approx.ftz.f32 %0, %1;" : "=f"(y) : "f"(x)); return y;
}
static __device__ __forceinline__ uint32_t s2u(const void* p) {
    uint32_t a;
    asm("{ .reg .u64 t; cvta.to.shared.u64 t, %1; cvt.u32.u64 %0, t; }" : "=r"(a) : "l"(p));
    return a;
}

__device__ __forceinline__ float blk_reduce_sum(float v, float* red) {
    int tid = threadIdx.x;
    red[tid] = v; __syncthreads();
    for (int s = blockDim.x >> 1; s > 0; s >>= 1) {
        if (tid < s) red[tid] += red[tid + s];
        __syncthreads();
    }
    float r = red[0]; __syncthreads(); return r;
}
__device__ __forceinline__ float blk_reduce_max(float v, float* red) {
    int tid = threadIdx.x;
    red[tid] = v; __syncthreads();
    for (int s = blockDim.x >> 1; s > 0; s >>= 1) {
        if (tid < s) red[tid] = fmaxf(red[tid], red[tid + s]);
        __syncthreads();
    }
    float r = red[0]; __syncthreads(); return r;
}

#define LDSM4(r, a)                                                             \
    asm volatile("ldmatrix.sync.aligned.m8n8.x4.shared.b16 {%0,%1,%2,%3}, [%4];" \
                 : "=r"((r)[0]), "=r"((r)[1]), "=r"((r)[2]), "=r"((r)[3]) : "r"(a))

#define MMA16816(d, a, b)                                                       \
    asm volatile(                                                               \
        "mma.sync.aligned.m16n8k16.row.col.f32.bf16.bf16.f32 "                  \
        "{%0,%1,%2,%3}, {%4,%5,%6,%7}, {%8,%9}, {%0,%1,%2,%3};"                 \
        : "+f"((d)[0]), "+f"((d)[1]), "+f"((d)[2]), "+f"((d)[3])                \
        : "r"((a)[0]), "r"((a)[1]), "r"((a)[2]), "r"((a)[3]),                   \
          "r"((b)[0]), "r"((b)[1]))

#define CPASYNC16(dst, src) \
    asm volatile("cp.async.cg.shared.global [%0], [%1], 16;" :: "r"(dst), "l"(src))

// ---------------- 1) L2 normalize -> bf16 hi/mid/lo --------------------------
__global__ void l2norm_bf16_kernel(const float* __restrict__ in, int rows, int sel) {
    int row  = blockIdx.x * (blockDim.x >> 5) + (threadIdx.x >> 5);
    int lane = threadIdx.x & 31;
    if (row >= rows) return;
    const float* p = in + (size_t)row * DD;
    float v[8]; float s = 0.0f;
#pragma unroll
    for (int i = 0; i < 8; i++) { v[i] = p[lane + 32 * i]; s += v[i] * v[i]; }
#pragma unroll
    for (int o = 16; o > 0; o >>= 1) s += __shfl_xor_sync(0xffffffffu, s, o);
    float inv = 1.0f / fmaxf(sqrtf(s), 1e-12f);

    __nv_bfloat16* dst = (sel == 2) ? g_B2 : g_A2;
    size_t base = ((sel == 1) ? (size_t)BB * K3 : 0) + (size_t)row * K3;
#pragma unroll
    for (int i = 0; i < 8; i++) {
        float x = v[i] * inv;
        __nv_bfloat16 h = __float2bfloat16(x);
        float r1 = x - __bfloat162float(h);
        __nv_bfloat16 m = __float2bfloat16(r1);
        float r2 = r1 - __bfloat162float(m);
        dst[base + lane + 32 * i]       = h;
        dst[base + 256 + lane + 32 * i] = m;
        dst[base + 512 + lane + 32 * i] = __float2bfloat16(r2);
    }
}

__global__ void padc_kernel() {
    int i = blockIdx.x * blockDim.x + threadIdx.x;
    int n = (KPAD - KK) * K3;
    if (i < n) g_B2[(size_t)KK * K3 + i] = __float2bfloat16(0.0f);
}

// ---------------- 2) bf16 mma.sync GEMM: S = A2[32768,768] @ B2[3072,768]^T --
// 128x128 tile, BK=64 (128B rows, XOR-swizzled), 3-stage cp.async, 8 warps 2x4.
#define GSTAGE 3
#define STAGE_BYTES 32768   // A 16KB + B 16KB
#define NIT (K3 / 64)       // 12

__global__ __launch_bounds__(256) void gemm_mma_kernel() {
    extern __shared__ char smem[];
    const uint32_t sb = s2u(smem);
    const int tid = threadIdx.x;
    const int lane = tid & 31;
    const int wid = tid >> 5;
    const int wm = wid >> 2;          // 0..1
    const int wn = wid & 3;           // 0..3

    const int nTilesN = KPAD / 128;   // 24
    const int mBase = (int)(blockIdx.x / nTilesN) * 128;
    const int nBase = (int)(blockIdx.x % nTilesN) * 128;

    const __nv_bfloat16* gA = g_A2 + (size_t)mBase * K3;
    const __nv_bfloat16* gB = g_B2 + (size_t)nBase * K3;

    float acc[4][4][4] = {};

    auto load_stage = [&](int s, int kIter) {
        uint32_t so = sb + (uint32_t)s * STAGE_BYTES;
        int k0 = kIter * 64;
#pragma unroll
        for (int i = 0; i < 4; i++) {
            int q = tid * 4 + i;          // 0..1023
            int row = q >> 3;
            int c = q & 7;
            uint32_t dst = so + row * 128 + ((c ^ (row & 7)) << 4);
            CPASYNC16(dst, gA + (size_t)row * K3 + k0 + c * 8);
            CPASYNC16(dst + 16384, gB + (size_t)row * K3 + k0 + c * 8);
        }
        asm volatile("cp.async.commit_group;" ::: "memory");
    };

    load_stage(0, 0);
    load_stage(1, 1);

    for (int it = 0; it < NIT; it++) {
        if (it + 2 < NIT) asm volatile("cp.async.wait_group 1;" ::: "memory");
        else              asm volatile("cp.async.wait_group 0;" ::: "memory");
        __syncthreads();
        if (it + 2 < NIT) load_stage((it + 2) % GSTAGE, it + 2);

        uint32_t aB = sb + (uint32_t)(it % GSTAGE) * STAGE_BYTES;
        uint32_t bB = aB + 16384;
#pragma unroll
        for (int ks = 0; ks < 4; ks++) {
            uint32_t a[4][4], b[4][2];
            int cch = ks * 2 + (lane >> 4);    // 16B chunk for this lane
#pragma unroll
            for (int mi = 0; mi < 4; mi++) {
                int row = wm * 64 + mi * 16 + (lane & 15);
                uint32_t addr = aB + row * 128 + ((cch ^ (row & 7)) << 4);
                LDSM4(a[mi], addr);
            }
#pragma unroll
            for (int nj = 0; nj < 2; nj++) {
                int row = wn * 32 + nj * 16 + (lane & 15);
                uint32_t addr = bB + row * 128 + ((cch ^ (row & 7)) << 4);
                uint32_t r4[4];
                LDSM4(r4, addr);
                // x4 returns: m0=(n0-7,k0-7) m1=(n8-15,k0-7) m2=(n0-7,k8-15) m3=(n8-15,k8-15)
                // mma B operand per 8-col block = {k0-7, k8-15}
                b[nj * 2][0]     = r4[0]; b[nj * 2][1]     = r4[2];
                b[nj * 2 + 1][0] = r4[1]; b[nj * 2 + 1][1] = r4[3];
            }
#pragma unroll
            for (int mi = 0; mi < 4; mi++)
#pragma unroll
                for (int ni = 0; ni < 4; ni++)
                    MMA16816(acc[mi][ni], a[mi], b[ni]);
        }
        __syncthreads();
    }

    // epilogue: direct coalesced stores (thread holds n, n+1 pairs)
#pragma unroll
    for (int mi = 0; mi < 4; mi++) {
        int gm = mBase + wm * 64 + mi * 16 + (lane >> 2);
#pragma unroll
        for (int ni = 0; ni < 4; ni++) {
            int gn = nBase + wn * 32 + ni * 8 + (lane & 3) * 2;
            if (gn < KK) {
                float2 v0 = make_float2(acc[mi][ni][0], acc[mi][ni][1]);
                float2 v1 = make_float2(acc[mi][ni][2], acc[mi][ni][3]);
                *(float2*)&g_S[(size_t)gm * KK + gn] = v0;
                *(float2*)&g_S[(size_t)(gm + 8) * KK + gn] = v1;
            }
        }
    }
}

// ---------------- 3) Sinkhorn passes -----------------------------------------
__global__ void colsum_exp_kernel(int simRowOff) {
    int k4 = (blockIdx.x * blockDim.x + threadIdx.x) * 4;
    if (k4 >= KK) return;
    int r0 = blockIdx.y * SLABROWS;
    const float* p = g_S + (size_t)(simRowOff + r0) * KK + k4;
    float* pe = g_E + (size_t)r0 * KK + k4;
    float4 acc = make_float4(0.f, 0.f, 0.f, 0.f);
#pragma unroll 4
    for (int r = 0; r < SLABROWS; r++) {
        float4 s = *(const float4*)(p + (size_t)r * KK);
        float4 e;
        e.x = ex2f(s.x * C_EXP20); e.y = ex2f(s.y * C_EXP20);
        e.z = ex2f(s.z * C_EXP20); e.w = ex2f(s.w * C_EXP20);
        *(float4*)(pe + (size_t)r * KK) = e;
        acc.x += e.x; acc.y += e.y; acc.z += e.z; acc.w += e.w;
    }
    *(float4*)(g_part + blockIdx.y * KK + k4) = acc;
}

__global__ void colsum_v_kernel() {
    int k4 = (blockIdx.x * blockDim.x + threadIdx.x) * 4;
    if (k4 >= KK) return;
    int r0 = blockIdx.y * SLABROWS;
    const float* pe = g_E + (size_t)r0 * KK + k4;
    float4 acc = make_float4(0.f, 0.f, 0.f, 0.f);
#pragma unroll 4
    for (int r = 0; r < SLABROWS; r++) {
        float vv = g_v[r0 + r];
        float4 e = *(const float4*)(pe + (size_t)r * KK);
        acc.x += vv * e.x; acc.y += vv * e.y; acc.z += vv * e.z; acc.w += vv * e.w;
    }
    *(float4*)(g_part + blockIdx.y * KK + k4) = acc;
}

__global__ void reduce_w_kernel() {
    int k4 = (blockIdx.x * blockDim.x + threadIdx.x) * 4;
    if (k4 >= KK) return;
    float4 s = make_float4(0.f, 0.f, 0.f, 0.f);
#pragma unroll 8
    for (int i = 0; i < NSLAB; i++) {
        float4 p = *(const float4*)(g_part + i * KK + k4);
        s.x += p.x; s.y += p.y; s.z += p.z; s.w += p.w;
    }
    *(float4*)(g_W + k4) = s;
}

__global__ void zreduce_kernel() {
    __shared__ float red[1024];
    float a = 0.0f;
    for (int k = threadIdx.x; k < KK; k += 1024) a += g_W[k];
    float z = blk_reduce_sum(a, red);
    if (threadIdx.x == 0) g_Z = z;
}

__global__ void compute_u_kernel() {
    int k = blockIdx.x * blockDim.x + threadIdx.x;
    if (k >= KK) return;
    float u = g_Z / ((float)KK * g_W[k]);
    g_u[k] = u;
    g_logu[k] = logf(u);
}

__global__ void rownorm_v_kernel() {
    __shared__ float red[256];
    int b = blockIdx.x;
    const float4* e = (const float4*)(g_E + (size_t)b * KK);
    const float4* u = (const float4*)g_u;
    float acc = 0.0f;
    for (int i = threadIdx.x; i < KK / 4; i += 256) {
        float4 ee = e[i], uu = u[i];
        acc += ee.x * uu.x + ee.y * uu.y + ee.z * uu.z + ee.w * uu.w;
    }
    float m = blk_reduce_sum(acc, red);
    if (threadIdx.x == 0) g_v[b] = g_Z / ((float)BB * m);
}

// ---------------- 4) fused final ---------------------------------------------
__global__ void final_row_kernel(int simRowOff, int predRowOff) {
    __shared__ float ssim[KK];
    __shared__ float sE[KK];
    __shared__ float spred[KK];
    __shared__ float red[256];
    int b = blockIdx.x, tid = threadIdx.x;
    {
        const float4* ps = (const float4*)(g_S + (size_t)(simRowOff + b) * KK);
        const float4* pe = (const float4*)(g_E + (size_t)b * KK);
        const float4* pp = (const float4*)(g_S + (size_t)(predRowOff + b) * KK);
        for (int i = tid; i < KK / 4; i += 256) {
            ((float4*)ssim)[i]  = ps[i];
            ((float4*)sE)[i]    = pe[i];
            ((float4*)spred)[i] = pp[i];
        }
    }
    __syncthreads();

    float a = 0.0f;
    for (int k = tid; k < KK; k += 256) a += g_u[k] * sE[k];
    float Mb = blk_reduce_sum(a, red);

    float mx = -1e30f;
    for (int k = tid; k < KK; k += 256) mx = fmaxf(mx, spred[k]);
    float m2 = C_EXP10 * blk_reduce_max(mx, red);
    float se = 0.0f;
    for (int k = tid; k < KK; k += 256) se += ex2f(spred[k] * C_EXP10 - m2);
    float ssum = blk_reduce_sum(se, red);
    float lse_nat = C_LN2 * (m2 + log2f(ssum));

    float invMb = 1.0f / Mb;
    float logMb = logf(Mb);
    float L = 0.0f;
    for (int k = tid; k < KK; k += 256) {
        float code = g_u[k] * sE[k] * invMb;
        float logc = g_logu[k] + 20.0f * ssim[k] - logMb;
        float logp = 10.0f * spred[k] - lse_nat;
        L += code * (logc - logp);
    }
    float Lb = blk_reduce_sum(L, red);
    if (tid == 0) g_rowloss[b] = Lb;
}

__global__ void loss_reduce_kernel(int lossIdx) {
    __shared__ float red[1024];
    float a = 0.0f;
    for (int b = threadIdx.x; b < BB; b += 1024) a += g_rowloss[b];
    float s = blk_reduce_sum(a, red);
    if (threadIdx.x == 0) g_loss[lossIdx] = s / (float)BB;
}

__global__ void combine_kernel(float* out) {
    out[0] = 0.5f * (g_loss[0] + g_loss[1]);
}

// ---------------- launch ------------------------------------------------------
extern "C" void kernel_launch(void* const* d_in, const int* in_sizes, int n_in,
                              void* d_out, int out_size) {
    const float* q = (const float*)d_in[0];
    const float* k = (const float*)d_in[1];
    const float* c = (const float*)d_in[2];

    cudaFuncSetAttribute(gemm_mma_kernel, cudaFuncAttributeMaxDynamicSharedMemorySize,
                         GSTAGE * STAGE_BYTES);

    l2norm_bf16_kernel<<<BB / 8, 256>>>(q, BB, 0);
    l2norm_bf16_kernel<<<BB / 8, 256>>>(k, BB, 1);
    l2norm_bf16_kernel<<<(KK + 7) / 8, 256>>>(c, KK, 2);
    padc_kernel<<<(((KPAD - KK) * K3) + 255) / 256, 256>>>();

    gemm_mma_kernel<<<(2 * BB / 128) * (KPAD / 128), 256, GSTAGE * STAGE_BYTES>>>();

    dim3 cg(6, NSLAB);
    for (int l = 0; l < 2; l++) {
        int simOff  = (l == 0) ? BB : 0;
        int predOff = (l == 0) ? 0 : BB;

        colsum_exp_kernel<<<cg, 128>>>(simOff);
        reduce_w_kernel<<<6, 128>>>();
        zreduce_kernel<<<1, 1024>>>();
        compute_u_kernel<<<(KK + 127) / 128, 128>>>();
        rownorm_v_kernel<<<BB, 256>>>();

        colsum_v_kernel<<<cg, 128>>>();
        reduce_w_kernel<<<6, 128>>>();
        compute_u_kernel<<<(KK + 127) / 128, 128>>>();
        rownorm_v_kernel<<<BB, 256>>>();

        colsum_v_kernel<<<cg, 128>>>();
        reduce_w_kernel<<<6, 128>>>();
        compute_u_kernel<<<(KK + 127) / 128, 128>>>();

        final_row_kernel<<<BB, 256>>>(simOff, predOff);
        loss_reduce_kernel<<<1, 1024>>>(l);
    }
    combine_kernel<<<1, 1>>>((float*)d_out);
}

// round 5
// speedup vs baseline: 1.4703x; 1.2106x over previous
#include <cuda_runtime.h>
#include <cuda_bf16.h>
#include <cstdint>

#define BB 16384
#define DD 256
#define KK 3000
#define KPAD 3072
#define K2 512           // hi|lo concatenated K
#define NSLAB 64
#define SLABROWS 256

#define C_EXP20 28.853900817779268f   // 20/ln2
#define C_EXP10 14.426950408889634f   // 10/ln2
#define C_LN2   0.6931471805599453f

// ---------------- device scratch -------------------------------------------
__device__ __align__(16) __nv_bfloat16 g_A2[(size_t)2 * BB * K2];   // [hi|lo] per row
__device__ __align__(16) __nv_bfloat16 g_B2[(size_t)KPAD * K2];
__device__ float g_S[(size_t)2 * BB * KK];   // rows 0..B-1 = nq@c^T ; B..2B-1 = nk@c^T
__device__ float g_E[(size_t)BB * KK];
__device__ float g_part[NSLAB * KK];
__device__ float g_W[KK];
__device__ float g_u[KK];
__device__ float g_logu[KK];
__device__ float g_v[BB];
__device__ float g_Z;
__device__ float g_rowloss[BB];
__device__ float g_loss[2];

// ---------------- helpers ----------------------------------------------------
static __device__ __forceinline__ float ex2f(float x) {
    float y; asm("ex2.approx.ftz.f32 %0, %1;" : "=f"(y) : "f"(x)); return y;
}
static __device__ __forceinline__ float lg2f(float x) {
    float y; asm("lg2.approx.ftz.f32 %0, %1;" : "=f"(y) : "f"(x)); return y;
}
static __device__ __forceinline__ uint32_t s2u(const void* p) {
    uint32_t a;
    asm("{ .reg .u64 t; cvta.to.shared.u64 t, %1; cvt.u32.u64 %0, t; }" : "=r"(a) : "l"(p));
    return a;
}

__device__ __forceinline__ float blk_reduce_sum(float v, float* red) {
    int tid = threadIdx.x;
    red[tid] = v; __syncthreads();
    for (int s = blockDim.x >> 1; s > 0; s >>= 1) {
        if (tid < s) red[tid] += red[tid + s];
        __syncthreads();
    }
    float r = red[0]; __syncthreads(); return r;
}
__device__ __forceinline__ float blk_reduce_max(float v, float* red) {
    int tid = threadIdx.x;
    red[tid] = v; __syncthreads();
    for (int s = blockDim.x >> 1; s > 0; s >>= 1) {
        if (tid < s) red[tid] = fmaxf(red[tid], red[tid + s]);
        __syncthreads();
    }
    float r = red[0]; __syncthreads(); return r;
}

#define LDSM4(r, a)                                                             \
    asm volatile("ldmatrix.sync.aligned.m8n8.x4.shared.b16 {%0,%1,%2,%3}, [%4];" \
                 : "=r"((r)[0]), "=r"((r)[1]), "=r"((r)[2]), "=r"((r)[3]) : "r"(a))

#define MMA16816(d, a, b)                                                       \
    asm volatile(                                                               \
        "mma.sync.aligned.m16n8k16.row.col.f32.bf16.bf16.f32 "                  \
        "{%0,%1,%2,%3}, {%4,%5,%6,%7}, {%8,%9}, {%0,%1,%2,%3};"                 \
        : "+f"((d)[0]), "+f"((d)[1]), "+f"((d)[2]), "+f"((d)[3])                \
        : "r"((a)[0]), "r"((a)[1]), "r"((a)[2]), "r"((a)[3]),                   \
          "r"((b)[0]), "r"((b)[1]))

#define CPASYNC16(dst, src) \
    asm volatile("cp.async.cg.shared.global [%0], [%1], 16;" :: "r"(dst), "l"(src))

// ---------------- 1) L2 normalize -> bf16 hi/lo ------------------------------
__global__ void l2norm_bf16_kernel(const float* __restrict__ in, int rows, int sel) {
    int row  = blockIdx.x * (blockDim.x >> 5) + (threadIdx.x >> 5);
    int lane = threadIdx.x & 31;
    if (row >= rows) return;
    const float* p = in + (size_t)row * DD;
    float v[8]; float s = 0.0f;
#pragma unroll
    for (int i = 0; i < 8; i++) { v[i] = p[lane + 32 * i]; s += v[i] * v[i]; }
#pragma unroll
    for (int o = 16; o > 0; o >>= 1) s += __shfl_xor_sync(0xffffffffu, s, o);
    float inv = 1.0f / fmaxf(sqrtf(s), 1e-12f);

    __nv_bfloat16* dst = (sel == 2) ? g_B2 : g_A2;
    size_t base = ((sel == 1) ? (size_t)BB * K2 : 0) + (size_t)row * K2;
#pragma unroll
    for (int i = 0; i < 8; i++) {
        float x = v[i] * inv;
        __nv_bfloat16 h = __float2bfloat16(x);
        float r1 = x - __bfloat162float(h);
        dst[base + lane + 32 * i]       = h;
        dst[base + 256 + lane + 32 * i] = __float2bfloat16(r1);
    }
}

__global__ void padc_kernel() {
    int i = blockIdx.x * blockDim.x + threadIdx.x;
    int n = (KPAD - KK) * K2;
    if (i < n) g_B2[(size_t)KK * K2 + i] = __float2bfloat16(0.0f);
}

// ---------------- 2) bf16 mma.sync GEMM: S = A2[32768,512] @ B2[3072,512]^T --
// 128x128 tile, BK=64 (128B rows, XOR-swizzled), 3-stage cp.async, 8 warps 2x4.
#define GSTAGE 3
#define STAGE_BYTES 32768   // A 16KB + B 16KB
#define NIT (K2 / 64)       // 8

__global__ __launch_bounds__(256) void gemm_mma_kernel() {
    extern __shared__ char smem[];
    const uint32_t sb = s2u(smem);
    const int tid = threadIdx.x;
    const int lane = tid & 31;
    const int wid = tid >> 5;
    const int wm = wid >> 2;          // 0..1
    const int wn = wid & 3;           // 0..3

    const int nTilesN = KPAD / 128;   // 24
    const int mBase = (int)(blockIdx.x / nTilesN) * 128;
    const int nBase = (int)(blockIdx.x % nTilesN) * 128;

    const __nv_bfloat16* gA = g_A2 + (size_t)mBase * K2;
    const __nv_bfloat16* gB = g_B2 + (size_t)nBase * K2;

    float acc[4][4][4] = {};

    auto load_stage = [&](int s, int kIter) {
        uint32_t so = sb + (uint32_t)s * STAGE_BYTES;
        int k0 = kIter * 64;
#pragma unroll
        for (int i = 0; i < 4; i++) {
            int q = tid * 4 + i;          // 0..1023
            int row = q >> 3;
            int c = q & 7;
            uint32_t dst = so + row * 128 + ((c ^ (row & 7)) << 4);
            CPASYNC16(dst, gA + (size_t)row * K2 + k0 + c * 8);
            CPASYNC16(dst + 16384, gB + (size_t)row * K2 + k0 + c * 8);
        }
        asm volatile("cp.async.commit_group;" ::: "memory");
    };

    load_stage(0, 0);
    load_stage(1, 1);

    for (int it = 0; it < NIT; it++) {
        if (it + 2 < NIT) asm volatile("cp.async.wait_group 1;" ::: "memory");
        else              asm volatile("cp.async.wait_group 0;" ::: "memory");
        __syncthreads();
        if (it + 2 < NIT) load_stage((it + 2) % GSTAGE, it + 2);

        uint32_t aB = sb + (uint32_t)(it % GSTAGE) * STAGE_BYTES;
        uint32_t bB = aB + 16384;
#pragma unroll
        for (int ks = 0; ks < 4; ks++) {
            uint32_t a[4][4], b[4][2];
            int cch = ks * 2 + (lane >> 4);    // 16B chunk for this lane
#pragma unroll
            for (int mi = 0; mi < 4; mi++) {
                int row = wm * 64 + mi * 16 + (lane & 15);
                uint32_t addr = aB + row * 128 + ((cch ^ (row & 7)) << 4);
                LDSM4(a[mi], addr);
            }
#pragma unroll
            for (int nj = 0; nj < 2; nj++) {
                int row = wn * 32 + nj * 16 + (lane & 15);
                uint32_t addr = bB + row * 128 + ((cch ^ (row & 7)) << 4);
                uint32_t r4[4];
                LDSM4(r4, addr);
                // x4 returns: m0=(n0-7,k0-7) m1=(n8-15,k0-7) m2=(n0-7,k8-15) m3=(n8-15,k8-15)
                b[nj * 2][0]     = r4[0]; b[nj * 2][1]     = r4[2];
                b[nj * 2 + 1][0] = r4[1]; b[nj * 2 + 1][1] = r4[3];
            }
#pragma unroll
            for (int mi = 0; mi < 4; mi++)
#pragma unroll
                for (int ni = 0; ni < 4; ni++)
                    MMA16816(acc[mi][ni], a[mi], b[ni]);
        }
        __syncthreads();
    }

    // epilogue: direct coalesced stores
#pragma unroll
    for (int mi = 0; mi < 4; mi++) {
        int gm = mBase + wm * 64 + mi * 16 + (lane >> 2);
#pragma unroll
        for (int ni = 0; ni < 4; ni++) {
            int gn = nBase + wn * 32 + ni * 8 + (lane & 3) * 2;
            if (gn < KK) {
                float2 v0 = make_float2(acc[mi][ni][0], acc[mi][ni][1]);
                float2 v1 = make_float2(acc[mi][ni][2], acc[mi][ni][3]);
                *(float2*)&g_S[(size_t)gm * KK + gn] = v0;
                *(float2*)&g_S[(size_t)(gm + 8) * KK + gn] = v1;
            }
        }
    }
}

// ---------------- 3) Sinkhorn passes -----------------------------------------
__global__ void colsum_exp_kernel(int simRowOff) {
    int k4 = (blockIdx.x * blockDim.x + threadIdx.x) * 4;
    if (k4 >= KK) return;
    int r0 = blockIdx.y * SLABROWS;
    const float* p = g_S + (size_t)(simRowOff + r0) * KK + k4;
    float* pe = g_E + (size_t)r0 * KK + k4;
    float4 acc = make_float4(0.f, 0.f, 0.f, 0.f);
#pragma unroll 4
    for (int r = 0; r < SLABROWS; r++) {
        float4 s = *(const float4*)(p + (size_t)r * KK);
        float4 e;
        e.x = ex2f(s.x * C_EXP20); e.y = ex2f(s.y * C_EXP20);
        e.z = ex2f(s.z * C_EXP20); e.w = ex2f(s.w * C_EXP20);
        *(float4*)(pe + (size_t)r * KK) = e;
        acc.x += e.x; acc.y += e.y; acc.z += e.z; acc.w += e.w;
    }
    *(float4*)(g_part + blockIdx.y * KK + k4) = acc;
}

__global__ void colsum_v_kernel() {
    int k4 = (blockIdx.x * blockDim.x + threadIdx.x) * 4;
    if (k4 >= KK) return;
    int r0 = blockIdx.y * SLABROWS;
    const float* pe = g_E + (size_t)r0 * KK + k4;
    float4 acc = make_float4(0.f, 0.f, 0.f, 0.f);
#pragma unroll 4
    for (int r = 0; r < SLABROWS; r++) {
        float vv = g_v[r0 + r];
        float4 e = *(const float4*)(pe + (size_t)r * KK);
        acc.x += vv * e.x; acc.y += vv * e.y; acc.z += vv * e.z; acc.w += vv * e.w;
    }
    *(float4*)(g_part + blockIdx.y * KK + k4) = acc;
}

__global__ void reduce_w_kernel() {
    int k4 = (blockIdx.x * blockDim.x + threadIdx.x) * 4;
    if (k4 >= KK) return;
    float4 s = make_float4(0.f, 0.f, 0.f, 0.f);
#pragma unroll 8
    for (int i = 0; i < NSLAB; i++) {
        float4 p = *(const float4*)(g_part + i * KK + k4);
        s.x += p.x; s.y += p.y; s.z += p.z; s.w += p.w;
    }
    *(float4*)(g_W + k4) = s;
}

__global__ void zreduce_kernel() {
    __shared__ float red[1024];
    float a = 0.0f;
    for (int k = threadIdx.x; k < KK; k += 1024) a += g_W[k];
    float z = blk_reduce_sum(a, red);
    if (threadIdx.x == 0) g_Z = z;
}

__global__ void compute_u_kernel() {
    int k = blockIdx.x * blockDim.x + threadIdx.x;
    if (k >= KK) return;
    float u = g_Z / ((float)KK * g_W[k]);
    g_u[k] = u;
    g_logu[k] = logf(u);
}

__global__ void rownorm_v_kernel() {
    __shared__ float red[256];
    int b = blockIdx.x;
    const float4* e = (const float4*)(g_E + (size_t)b * KK);
    const float4* u = (const float4*)g_u;
    float acc = 0.0f;
    for (int i = threadIdx.x; i < KK / 4; i += 256) {
        float4 ee = e[i], uu = u[i];
        acc += ee.x * uu.x + ee.y * uu.y + ee.z * uu.z + ee.w * uu.w;
    }
    float m = blk_reduce_sum(acc, red);
    if (threadIdx.x == 0) g_v[b] = g_Z / ((float)BB * m);
}

// ---------------- 4) fused final (sim recovered from E: 20*sim = ln2*log2 E) -
__global__ void final_row_kernel(int predRowOff) {
    __shared__ float sE[KK];
    __shared__ float spred[KK];
    __shared__ float red[256];
    int b = blockIdx.x, tid = threadIdx.x;
    {
        const float4* pe = (const float4*)(g_E + (size_t)b * KK);
        const float4* pp = (const float4*)(g_S + (size_t)(predRowOff + b) * KK);
        for (int i = tid; i < KK / 4; i += 256) {
            ((float4*)sE)[i]    = pe[i];
            ((float4*)spred)[i] = pp[i];
        }
    }
    __syncthreads();

    float a = 0.0f;
    for (int k = tid; k < KK; k += 256) a += g_u[k] * sE[k];
    float Mb = blk_reduce_sum(a, red);

    float mx = -1e30f;
    for (int k = tid; k < KK; k += 256) mx = fmaxf(mx, spred[k]);
    float m2 = C_EXP10 * blk_reduce_max(mx, red);
    float se = 0.0f;
    for (int k = tid; k < KK; k += 256) se += ex2f(spred[k] * C_EXP10 - m2);
    float ssum = blk_reduce_sum(se, red);
    float lse_nat = C_LN2 * (m2 + log2f(ssum));

    float invMb = 1.0f / Mb;
    float logMb = logf(Mb);
    float L = 0.0f;
    for (int k = tid; k < KK; k += 256) {
        float e = sE[k];
        float code = g_u[k] * e * invMb;
        float logc = g_logu[k] + C_LN2 * lg2f(e) - logMb;   // 20*sim = ln(E)
        float logp = 10.0f * spred[k] - lse_nat;
        L += code * (logc - logp);
    }
    float Lb = blk_reduce_sum(L, red);
    if (tid == 0) g_rowloss[b] = Lb;
}

__global__ void loss_reduce_kernel(int lossIdx) {
    __shared__ float red[1024];
    float a = 0.0f;
    for (int b = threadIdx.x; b < BB; b += 1024) a += g_rowloss[b];
    float s = blk_reduce_sum(a, red);
    if (threadIdx.x == 0) g_loss[lossIdx] = s / (float)BB;
}

__global__ void combine_kernel(float* out) {
    out[0] = 0.5f * (g_loss[0] + g_loss[1]);
}

// ---------------- launch ------------------------------------------------------
extern "C" void kernel_launch(void* const* d_in, const int* in_sizes, int n_in,
                              void* d_out, int out_size) {
    const float* q = (const float*)d_in[0];
    const float* k = (const float*)d_in[1];
    const float* c = (const float*)d_in[2];

    cudaFuncSetAttribute(gemm_mma_kernel, cudaFuncAttributeMaxDynamicSharedMemorySize,
                         GSTAGE * STAGE_BYTES);

    l2norm_bf16_kernel<<<BB / 8, 256>>>(q, BB, 0);
    l2norm_bf16_kernel<<<BB / 8, 256>>>(k, BB, 1);
    l2norm_bf16_kernel<<<(KK + 7) / 8, 256>>>(c, KK, 2);
    padc_kernel<<<(((KPAD - KK) * K2) + 255) / 256, 256>>>();

    gemm_mma_kernel<<<(2 * BB / 128) * (KPAD / 128), 256, GSTAGE * STAGE_BYTES>>>();

    dim3 cg(6, NSLAB);
    for (int l = 0; l < 2; l++) {
        int simOff  = (l == 0) ? BB : 0;
        int predOff = (l == 0) ? 0 : BB;

        colsum_exp_kernel<<<cg, 128>>>(simOff);
        reduce_w_kernel<<<6, 128>>>();
        zreduce_kernel<<<1, 1024>>>();
        compute_u_kernel<<<(KK + 127) / 128, 128>>>();
        rownorm_v_kernel<<<BB, 256>>>();

        colsum_v_kernel<<<cg, 128>>>();
        reduce_w_kernel<<<6, 128>>>();
        compute_u_kernel<<<(KK + 127) / 128, 128>>>();
        rownorm_v_kernel<<<BB, 256>>>();

        colsum_v_kernel<<<cg, 128>>>();
        reduce_w_kernel<<<6, 128>>>();
        compute_u_kernel<<<(KK + 127) / 128, 128>>>();

        final_row_kernel<<<BB, 256>>>(predOff);
        loss_reduce_kernel<<<1, 1024>>>(l);
    }
    combine_kernel<<<1, 1>>>((float*)d_out);
}

// round 6
// speedup vs baseline: 1.7172x; 1.1679x over previous
#include <cuda_runtime.h>
#include <cuda_bf16.h>
#include <cstdint>

#define BB 16384
#define DD 256
#define KK 3000
#define KPAD 3072
#define NSLAB 64
#define SLABROWS 256

#define C_EXP20 28.853900817779268f   // 20/ln2
#define C_EXP10 14.426950408889634f   // 10/ln2
#define C_LN2   0.6931471805599453f

// ---------------- device scratch -------------------------------------------
__device__ __align__(16) __nv_bfloat16 g_A2[(size_t)2 * BB * DD];
__device__ __align__(16) __nv_bfloat16 g_B2[(size_t)KPAD * DD];
__device__ float g_S[(size_t)2 * BB * KK];   // rows 0..B-1 = nq@c^T ; B..2B-1 = nk@c^T
__device__ __align__(16) __nv_bfloat16 g_E[(size_t)BB * KK];   // exp(sim/eps), bf16
__device__ float g_part[NSLAB * KK];
__device__ float g_W[KK];
__device__ float g_u[KK];
__device__ float g_logu[KK];
__device__ float g_v[BB];
__device__ float g_Z;
__device__ float g_rowloss[BB];
__device__ float g_loss[2];

// ---------------- helpers ----------------------------------------------------
static __device__ __forceinline__ float ex2f(float x) {
    float y; asm("ex2.approx.ftz.f32 %0, %1;" : "=f"(y) : "f"(x)); return y;
}
static __device__ __forceinline__ float lg2f(float x) {
    float y; asm("lg2.approx.ftz.f32 %0, %1;" : "=f"(y) : "f"(x)); return y;
}
static __device__ __forceinline__ uint32_t s2u(const void* p) {
    uint32_t a;
    asm("{ .reg .u64 t; cvta.to.shared.u64 t, %1; cvt.u32.u64 %0, t; }" : "=r"(a) : "l"(p));
    return a;
}

__device__ __forceinline__ float blk_reduce_sum(float v, float* red) {
    int tid = threadIdx.x;
    red[tid] = v; __syncthreads();
    for (int s = blockDim.x >> 1; s > 0; s >>= 1) {
        if (tid < s) red[tid] += red[tid + s];
        __syncthreads();
    }
    float r = red[0]; __syncthreads(); return r;
}
__device__ __forceinline__ float blk_reduce_max(float v, float* red) {
    int tid = threadIdx.x;
    red[tid] = v; __syncthreads();
    for (int s = blockDim.x >> 1; s > 0; s >>= 1) {
        if (tid < s) red[tid] = fmaxf(red[tid], red[tid + s]);
        __syncthreads();
    }
    float r = red[0]; __syncthreads(); return r;
}

#define LDSM4(r, a)                                                             \
    asm volatile("ldmatrix.sync.aligned.m8n8.x4.shared.b16 {%0,%1,%2,%3}, [%4];" \
                 : "=r"((r)[0]), "=r"((r)[1]), "=r"((r)[2]), "=r"((r)[3]) : "r"(a))

#define MMA16816(d, a, b)                                                       \
    asm volatile(                                                               \
        "mma.sync.aligned.m16n8k16.row.col.f32.bf16.bf16.f32 "                  \
        "{%0,%1,%2,%3}, {%4,%5,%6,%7}, {%8,%9}, {%0,%1,%2,%3};"                 \
        : "+f"((d)[0]), "+f"((d)[1]), "+f"((d)[2]), "+f"((d)[3])                \
        : "r"((a)[0]), "r"((a)[1]), "r"((a)[2]), "r"((a)[3]),                   \
          "r"((b)[0]), "r"((b)[1]))

#define CPASYNC16(dst, src) \
    asm volatile("cp.async.cg.shared.global [%0], [%1], 16;" :: "r"(dst), "l"(src))

// ---------------- 1) L2 normalize -> bf16 ------------------------------------
__global__ void l2norm_bf16_kernel(const float* __restrict__ in, int rows, int sel) {
    int row  = blockIdx.x * (blockDim.x >> 5) + (threadIdx.x >> 5);
    int lane = threadIdx.x & 31;
    if (row >= rows) return;
    const float* p = in + (size_t)row * DD;
    float v[8]; float s = 0.0f;
#pragma unroll
    for (int i = 0; i < 8; i++) { v[i] = p[lane + 32 * i]; s += v[i] * v[i]; }
#pragma unroll
    for (int o = 16; o > 0; o >>= 1) s += __shfl_xor_sync(0xffffffffu, s, o);
    float inv = 1.0f / fmaxf(sqrtf(s), 1e-12f);

    __nv_bfloat16* dst = (sel == 2) ? g_B2 : g_A2;
    size_t base = ((sel == 1) ? (size_t)BB * DD : 0) + (size_t)row * DD;
#pragma unroll
    for (int i = 0; i < 8; i++)
        dst[base + lane + 32 * i] = __float2bfloat16(v[i] * inv);
}

__global__ void padc_kernel() {
    int i = blockIdx.x * blockDim.x + threadIdx.x;
    int n = (KPAD - KK) * DD;
    if (i < n) g_B2[(size_t)KK * DD + i] = __float2bfloat16(0.0f);
}

// ---------------- 2) bf16 mma.sync GEMM: S = A2[32768,256] @ B2[3072,256]^T --
// 128x128 tile, BK=64 (128B rows, XOR-swizzled), 3-stage cp.async, 8 warps 2x4.
#define GSTAGE 3
#define STAGE_BYTES 32768   // A 16KB + B 16KB
#define NIT (DD / 64)       // 4

__global__ __launch_bounds__(256) void gemm_mma_kernel() {
    extern __shared__ char smem[];
    const uint32_t sb = s2u(smem);
    const int tid = threadIdx.x;
    const int lane = tid & 31;
    const int wid = tid >> 5;
    const int wm = wid >> 2;          // 0..1
    const int wn = wid & 3;           // 0..3

    const int nTilesN = KPAD / 128;   // 24
    const int mBase = (int)(blockIdx.x / nTilesN) * 128;
    const int nBase = (int)(blockIdx.x % nTilesN) * 128;

    const __nv_bfloat16* gA = g_A2 + (size_t)mBase * DD;
    const __nv_bfloat16* gB = g_B2 + (size_t)nBase * DD;

    float acc[4][4][4] = {};

    auto load_stage = [&](int s, int kIter) {
        uint32_t so = sb + (uint32_t)s * STAGE_BYTES;
        int k0 = kIter * 64;
#pragma unroll
        for (int i = 0; i < 4; i++) {
            int q = tid * 4 + i;          // 0..1023
            int row = q >> 3;
            int c = q & 7;
            uint32_t dst = so + row * 128 + ((c ^ (row & 7)) << 4);
            CPASYNC16(dst, gA + (size_t)row * DD + k0 + c * 8);
            CPASYNC16(dst + 16384, gB + (size_t)row * DD + k0 + c * 8);
        }
        asm volatile("cp.async.commit_group;" ::: "memory");
    };

    load_stage(0, 0);
    load_stage(1, 1);

    for (int it = 0; it < NIT; it++) {
        if (it + 2 < NIT) asm volatile("cp.async.wait_group 1;" ::: "memory");
        else              asm volatile("cp.async.wait_group 0;" ::: "memory");
        __syncthreads();
        if (it + 2 < NIT) load_stage((it + 2) % GSTAGE, it + 2);

        uint32_t aB = sb + (uint32_t)(it % GSTAGE) * STAGE_BYTES;
        uint32_t bB = aB + 16384;
#pragma unroll
        for (int ks = 0; ks < 4; ks++) {
            uint32_t a[4][4], b[4][2];
            int cch = ks * 2 + (lane >> 4);    // 16B chunk for this lane
#pragma unroll
            for (int mi = 0; mi < 4; mi++) {
                int row = wm * 64 + mi * 16 + (lane & 15);
                uint32_t addr = aB + row * 128 + ((cch ^ (row & 7)) << 4);
                LDSM4(a[mi], addr);
            }
#pragma unroll
            for (int nj = 0; nj < 2; nj++) {
                int row = wn * 32 + nj * 16 + (lane & 15);
                uint32_t addr = bB + row * 128 + ((cch ^ (row & 7)) << 4);
                uint32_t r4[4];
                LDSM4(r4, addr);
                // x4 returns: m0=(n0-7,k0-7) m1=(n8-15,k0-7) m2=(n0-7,k8-15) m3=(n8-15,k8-15)
                b[nj * 2][0]     = r4[0]; b[nj * 2][1]     = r4[2];
                b[nj * 2 + 1][0] = r4[1]; b[nj * 2 + 1][1] = r4[3];
            }
#pragma unroll
            for (int mi = 0; mi < 4; mi++)
#pragma unroll
                for (int ni = 0; ni < 4; ni++)
                    MMA16816(acc[mi][ni], a[mi], b[ni]);
        }
        __syncthreads();
    }

    // epilogue: direct coalesced stores
#pragma unroll
    for (int mi = 0; mi < 4; mi++) {
        int gm = mBase + wm * 64 + mi * 16 + (lane >> 2);
#pragma unroll
        for (int ni = 0; ni < 4; ni++) {
            int gn = nBase + wn * 32 + ni * 8 + (lane & 3) * 2;
            if (gn < KK) {
                float2 v0 = make_float2(acc[mi][ni][0], acc[mi][ni][1]);
                float2 v1 = make_float2(acc[mi][ni][2], acc[mi][ni][3]);
                *(float2*)&g_S[(size_t)gm * KK + gn] = v0;
                *(float2*)&g_S[(size_t)(gm + 8) * KK + gn] = v1;
            }
        }
    }
}

// ---------------- 3) Sinkhorn passes (E in bf16) -----------------------------
__global__ void colsum_exp_kernel(int simRowOff) {
    int k4 = (blockIdx.x * blockDim.x + threadIdx.x) * 4;
    if (k4 >= KK) return;
    int r0 = blockIdx.y * SLABROWS;
    const float* p = g_S + (size_t)(simRowOff + r0) * KK + k4;
    __nv_bfloat16* pe = g_E + (size_t)r0 * KK + k4;
    float4 acc = make_float4(0.f, 0.f, 0.f, 0.f);
#pragma unroll 4
    for (int r = 0; r < SLABROWS; r++) {
        float4 s = *(const float4*)(p + (size_t)r * KK);
        float ex = ex2f(s.x * C_EXP20), ey = ex2f(s.y * C_EXP20);
        float ez = ex2f(s.z * C_EXP20), ew = ex2f(s.w * C_EXP20);
        __nv_bfloat162 h0 = __floats2bfloat162_rn(ex, ey);
        __nv_bfloat162 h1 = __floats2bfloat162_rn(ez, ew);
        *(uint2*)(pe + (size_t)r * KK) = make_uint2(*(uint32_t*)&h0, *(uint32_t*)&h1);
        acc.x += ex; acc.y += ey; acc.z += ez; acc.w += ew;
    }
    *(float4*)(g_part + blockIdx.y * KK + k4) = acc;
}

__global__ void colsum_v_kernel() {
    int k8 = (blockIdx.x * blockDim.x + threadIdx.x) * 8;
    if (k8 >= KK) return;
    int r0 = blockIdx.y * SLABROWS;
    const __nv_bfloat16* pe = g_E + (size_t)r0 * KK + k8;
    float acc[8] = {};
#pragma unroll 2
    for (int r = 0; r < SLABROWS; r++) {
        float vv = g_v[r0 + r];
        uint4 raw = *(const uint4*)(pe + (size_t)r * KK);
        const __nv_bfloat162* h = (const __nv_bfloat162*)&raw;
#pragma unroll
        for (int j = 0; j < 4; j++) {
            float2 e = __bfloat1622float2(h[j]);
            acc[j * 2]     += vv * e.x;
            acc[j * 2 + 1] += vv * e.y;
        }
    }
    *(float4*)(g_part + blockIdx.y * KK + k8)     = make_float4(acc[0], acc[1], acc[2], acc[3]);
    *(float4*)(g_part + blockIdx.y * KK + k8 + 4) = make_float4(acc[4], acc[5], acc[6], acc[7]);
}

__global__ void reduce_w_kernel() {
    int k4 = (blockIdx.x * blockDim.x + threadIdx.x) * 4;
    if (k4 >= KK) return;
    float4 s = make_float4(0.f, 0.f, 0.f, 0.f);
#pragma unroll 8
    for (int i = 0; i < NSLAB; i++) {
        float4 p = *(const float4*)(g_part + i * KK + k4);
        s.x += p.x; s.y += p.y; s.z += p.z; s.w += p.w;
    }
    *(float4*)(g_W + k4) = s;
}

__global__ void zreduce_kernel() {
    __shared__ float red[1024];
    float a = 0.0f;
    for (int k = threadIdx.x; k < KK; k += 1024) a += g_W[k];
    float z = blk_reduce_sum(a, red);
    if (threadIdx.x == 0) g_Z = z;
}

__global__ void compute_u_kernel() {
    int k = blockIdx.x * blockDim.x + threadIdx.x;
    if (k >= KK) return;
    float u = g_Z / ((float)KK * g_W[k]);
    g_u[k] = u;
    g_logu[k] = logf(u);
}

__global__ void rownorm_v_kernel() {
    __shared__ float red[256];
    int b = blockIdx.x;
    const __nv_bfloat16* pe = g_E + (size_t)b * KK;
    const float4* u4 = (const float4*)g_u;
    float acc = 0.0f;
    for (int i = threadIdx.x; i < KK / 8; i += 256) {
        uint4 raw = *(const uint4*)(pe + i * 8);
        const __nv_bfloat162* h = (const __nv_bfloat162*)&raw;
        float4 u0 = u4[i * 2], u1 = u4[i * 2 + 1];
        float2 e0 = __bfloat1622float2(h[0]);
        float2 e1 = __bfloat1622float2(h[1]);
        float2 e2 = __bfloat1622float2(h[2]);
        float2 e3 = __bfloat1622float2(h[3]);
        acc += e0.x * u0.x + e0.y * u0.y + e1.x * u0.z + e1.y * u0.w
             + e2.x * u1.x + e2.y * u1.y + e3.x * u1.z + e3.y * u1.w;
    }
    float m = blk_reduce_sum(acc, red);
    if (threadIdx.x == 0) g_v[b] = g_Z / ((float)BB * m);
}

// ---------------- 4) fused final (20*sim = ln(E)) ----------------------------
__global__ void final_row_kernel(int predRowOff) {
    __shared__ __nv_bfloat16 sE[KK];
    __shared__ float spred[KK];
    __shared__ float red[256];
    int b = blockIdx.x, tid = threadIdx.x;
    {
        const uint4* pe = (const uint4*)(g_E + (size_t)b * KK);
        const float4* pp = (const float4*)(g_S + (size_t)(predRowOff + b) * KK);
        for (int i = tid; i < KK / 8; i += 256) ((uint4*)sE)[i] = pe[i];
        for (int i = tid; i < KK / 4; i += 256) ((float4*)spred)[i] = pp[i];
    }
    __syncthreads();

    float a = 0.0f;
    for (int k = tid; k < KK; k += 256) a += g_u[k] * __bfloat162float(sE[k]);
    float Mb = blk_reduce_sum(a, red);

    float mx = -1e30f;
    for (int k = tid; k < KK; k += 256) mx = fmaxf(mx, spred[k]);
    float m2 = C_EXP10 * blk_reduce_max(mx, red);
    float se = 0.0f;
    for (int k = tid; k < KK; k += 256) se += ex2f(spred[k] * C_EXP10 - m2);
    float ssum = blk_reduce_sum(se, red);
    float lse_nat = C_LN2 * (m2 + log2f(ssum));

    float invMb = 1.0f / Mb;
    float logMb = logf(Mb);
    float L = 0.0f;
    for (int k = tid; k < KK; k += 256) {
        float e = __bfloat162float(sE[k]);
        float code = g_u[k] * e * invMb;
        float logc = g_logu[k] + C_LN2 * lg2f(e) - logMb;
        float logp = 10.0f * spred[k] - lse_nat;
        L += code * (logc - logp);
    }
    float Lb = blk_reduce_sum(L, red);
    if (tid == 0) g_rowloss[b] = Lb;
}

__global__ void loss_reduce_kernel(int lossIdx) {
    __shared__ float red[1024];
    float a = 0.0f;
    for (int b = threadIdx.x; b < BB; b += 1024) a += g_rowloss[b];
    float s = blk_reduce_sum(a, red);
    if (threadIdx.x == 0) g_loss[lossIdx] = s / (float)BB;
}

__global__ void combine_kernel(float* out) {
    out[0] = 0.5f * (g_loss[0] + g_loss[1]);
}

// ---------------- launch ------------------------------------------------------
extern "C" void kernel_launch(void* const* d_in, const int* in_sizes, int n_in,
                              void* d_out, int out_size) {
    const float* q = (const float*)d_in[0];
    const float* k = (const float*)d_in[1];
    const float* c = (const float*)d_in[2];

    cudaFuncSetAttribute(gemm_mma_kernel, cudaFuncAttributeMaxDynamicSharedMemorySize,
                         GSTAGE * STAGE_BYTES);

    l2norm_bf16_kernel<<<BB / 8, 256>>>(q, BB, 0);
    l2norm_bf16_kernel<<<BB / 8, 256>>>(k, BB, 1);
    l2norm_bf16_kernel<<<(KK + 7) / 8, 256>>>(c, KK, 2);
    padc_kernel<<<(((KPAD - KK) * DD) + 255) / 256, 256>>>();

    gemm_mma_kernel<<<(2 * BB / 128) * (KPAD / 128), 256, GSTAGE * STAGE_BYTES>>>();

    dim3 cg4(6, NSLAB);   // colsum_exp: 4-wide
    dim3 cg8(3, NSLAB);   // colsum_v: 8-wide
    for (int l = 0; l < 2; l++) {
        int simOff  = (l == 0) ? BB : 0;
        int predOff = (l == 0) ? 0 : BB;

        colsum_exp_kernel<<<cg4, 128>>>(simOff);
        reduce_w_kernel<<<6, 128>>>();
        zreduce_kernel<<<1, 1024>>>();
        compute_u_kernel<<<(KK + 127) / 128, 128>>>();
        rownorm_v_kernel<<<BB, 256>>>();

        colsum_v_kernel<<<cg8, 128>>>();
        reduce_w_kernel<<<6, 128>>>();
        compute_u_kernel<<<(KK + 127) / 128, 128>>>();
        rownorm_v_kernel<<<BB, 256>>>();

        colsum_v_kernel<<<cg8, 128>>>();
        reduce_w_kernel<<<6, 128>>>();
        compute_u_kernel<<<(KK + 127) / 128, 128>>>();

        final_row_kernel<<<BB, 256>>>(predOff);
        loss_reduce_kernel<<<1, 1024>>>(l);
    }
    combine_kernel<<<1, 1>>>((float*)d_out);
}

// round 7
// speedup vs baseline: 2.4884x; 1.4491x over previous
#include <cuda_runtime.h>
#include <cuda_bf16.h>
#include <cstdint>

#define BB 16384
#define DD 256
#define KK 3000
#define KPAD 3072
#define NFB 512          // fused row/col blocks
#define RPB 32           // rows per fused block

#define C_EXP20 28.853900817779268f   // 20/ln2
#define C_EXP10 14.426950408889634f   // 10/ln2
#define C_LN2   0.6931471805599453f

// ---------------- device scratch -------------------------------------------
__device__ __align__(16) __nv_bfloat16 g_A2[(size_t)2 * BB * DD];
__device__ __align__(16) __nv_bfloat16 g_B2[(size_t)KPAD * DD];
__device__ __align__(16) __nv_bfloat16 g_E[(size_t)2 * BB * KK];  // exp(sim/eps) bf16
__device__ __align__(16) __nv_bfloat16 g_P[(size_t)2 * BB * KK];  // sim bf16 (pred use)
__device__ float g_partW[(size_t)256 * KPAD];   // per-GEMM-tile column partials of E
__device__ float g_part2[(size_t)NFB * KPAD];   // fused-pass column partials
__device__ float g_W[KK];
__device__ float g_u[KK];
__device__ float g_logu[KK];
__device__ float g_Z;
__device__ float g_rowloss[BB];
__device__ float g_loss[2];

// ---------------- helpers ----------------------------------------------------
static __device__ __forceinline__ float ex2f(float x) {
    float y; asm("ex2.approx.ftz.f32 %0, %1;" : "=f"(y) : "f"(x)); return y;
}
static __device__ __forceinline__ float lg2f(float x) {
    float y; asm("lg2.approx.ftz.f32 %0, %1;" : "=f"(y) : "f"(x)); return y;
}
static __device__ __forceinline__ uint32_t s2u(const void* p) {
    uint32_t a;
    asm("{ .reg .u64 t; cvta.to.shared.u64 t, %1; cvt.u32.u64 %0, t; }" : "=r"(a) : "l"(p));
    return a;
}

__device__ __forceinline__ float blk_reduce_sum(float v, float* red) {
    int tid = threadIdx.x;
    red[tid] = v; __syncthreads();
    for (int s = blockDim.x >> 1; s > 0; s >>= 1) {
        if (tid < s) red[tid] += red[tid + s];
        __syncthreads();
    }
    float r = red[0]; __syncthreads(); return r;
}
__device__ __forceinline__ float blk_reduce_max(float v, float* red) {
    int tid = threadIdx.x;
    red[tid] = v; __syncthreads();
    for (int s = blockDim.x >> 1; s > 0; s >>= 1) {
        if (tid < s) red[tid] = fmaxf(red[tid], red[tid + s]);
        __syncthreads();
    }
    float r = red[0]; __syncthreads(); return r;
}

#define LDSM4(r, a)                                                             \
    asm volatile("ldmatrix.sync.aligned.m8n8.x4.shared.b16 {%0,%1,%2,%3}, [%4];" \
                 : "=r"((r)[0]), "=r"((r)[1]), "=r"((r)[2]), "=r"((r)[3]) : "r"(a))

#define MMA16816(d, a, b)                                                       \
    asm volatile(                                                               \
        "mma.sync.aligned.m16n8k16.row.col.f32.bf16.bf16.f32 "                  \
        "{%0,%1,%2,%3}, {%4,%5,%6,%7}, {%8,%9}, {%0,%1,%2,%3};"                 \
        : "+f"((d)[0]), "+f"((d)[1]), "+f"((d)[2]), "+f"((d)[3])                \
        : "r"((a)[0]), "r"((a)[1]), "r"((a)[2]), "r"((a)[3]),                   \
          "r"((b)[0]), "r"((b)[1]))

#define CPASYNC16(dst, src) \
    asm volatile("cp.async.cg.shared.global [%0], [%1], 16;" :: "r"(dst), "l"(src))

// ---------------- 1) L2 normalize -> bf16 ------------------------------------
__global__ void l2norm_bf16_kernel(const float* __restrict__ in, int rows, int sel) {
    int row  = blockIdx.x * (blockDim.x >> 5) + (threadIdx.x >> 5);
    int lane = threadIdx.x & 31;
    if (row >= rows) return;
    const float* p = in + (size_t)row * DD;
    float v[8]; float s = 0.0f;
#pragma unroll
    for (int i = 0; i < 8; i++) { v[i] = p[lane + 32 * i]; s += v[i] * v[i]; }
#pragma unroll
    for (int o = 16; o > 0; o >>= 1) s += __shfl_xor_sync(0xffffffffu, s, o);
    float inv = 1.0f / fmaxf(sqrtf(s), 1e-12f);

    __nv_bfloat16* dst = (sel == 2) ? g_B2 : g_A2;
    size_t base = ((sel == 1) ? (size_t)BB * DD : 0) + (size_t)row * DD;
#pragma unroll
    for (int i = 0; i < 8; i++)
        dst[base + lane + 32 * i] = __float2bfloat16(v[i] * inv);
}

__global__ void padc_kernel() {
    int i = blockIdx.x * blockDim.x + threadIdx.x;
    int n = (KPAD - KK) * DD;
    if (i < n) g_B2[(size_t)KK * DD + i] = __float2bfloat16(0.0f);
}

// ---------------- 2) GEMM + fused epilogue (E, P, W1-partials) ---------------
#define GSTAGE 3
#define STAGE_BYTES 32768
#define NIT (DD / 64)       // 4

__global__ __launch_bounds__(256) void gemm_mma_kernel() {
    extern __shared__ char smem[];
    const uint32_t sb = s2u(smem);
    const int tid = threadIdx.x;
    const int lane = tid & 31;
    const int wid = tid >> 5;
    const int wm = wid >> 2;
    const int wn = wid & 3;

    const int nTilesN = KPAD / 128;   // 24
    const int mBase = (int)(blockIdx.x / nTilesN) * 128;
    const int nBase = (int)(blockIdx.x % nTilesN) * 128;

    const __nv_bfloat16* gA = g_A2 + (size_t)mBase * DD;
    const __nv_bfloat16* gB = g_B2 + (size_t)nBase * DD;

    float acc[4][4][4] = {};

    auto load_stage = [&](int s, int kIter) {
        uint32_t so = sb + (uint32_t)s * STAGE_BYTES;
        int k0 = kIter * 64;
#pragma unroll
        for (int i = 0; i < 4; i++) {
            int q = tid * 4 + i;
            int row = q >> 3;
            int c = q & 7;
            uint32_t dst = so + row * 128 + ((c ^ (row & 7)) << 4);
            CPASYNC16(dst, gA + (size_t)row * DD + k0 + c * 8);
            CPASYNC16(dst + 16384, gB + (size_t)row * DD + k0 + c * 8);
        }
        asm volatile("cp.async.commit_group;" ::: "memory");
    };

    load_stage(0, 0);
    load_stage(1, 1);

    for (int it = 0; it < NIT; it++) {
        if (it + 2 < NIT) asm volatile("cp.async.wait_group 1;" ::: "memory");
        else              asm volatile("cp.async.wait_group 0;" ::: "memory");
        __syncthreads();
        if (it + 2 < NIT) load_stage((it + 2) % GSTAGE, it + 2);

        uint32_t aB = sb + (uint32_t)(it % GSTAGE) * STAGE_BYTES;
        uint32_t bB = aB + 16384;
#pragma unroll
        for (int ks = 0; ks < 4; ks++) {
            uint32_t a[4][4], b[4][2];
            int cch = ks * 2 + (lane >> 4);
#pragma unroll
            for (int mi = 0; mi < 4; mi++) {
                int row = wm * 64 + mi * 16 + (lane & 15);
                uint32_t addr = aB + row * 128 + ((cch ^ (row & 7)) << 4);
                LDSM4(a[mi], addr);
            }
#pragma unroll
            for (int nj = 0; nj < 2; nj++) {
                int row = wn * 32 + nj * 16 + (lane & 15);
                uint32_t addr = bB + row * 128 + ((cch ^ (row & 7)) << 4);
                uint32_t r4[4];
                LDSM4(r4, addr);
                b[nj * 2][0]     = r4[0]; b[nj * 2][1]     = r4[2];
                b[nj * 2 + 1][0] = r4[1]; b[nj * 2 + 1][1] = r4[3];
            }
#pragma unroll
            for (int mi = 0; mi < 4; mi++)
#pragma unroll
                for (int ni = 0; ni < 4; ni++)
                    MMA16816(acc[mi][ni], a[mi], b[ni]);
        }
        __syncthreads();
    }

    // ---- fused epilogue: E = 2^(sim*20/ln2) bf16, P = sim bf16,
    //      per-tile column sums of E -> g_partW[mtile][col]
    float* cs = (float*)smem;   // [2][128], aliases stage smem (free after last sync)
    float cp0[4], cp1[4];
#pragma unroll
    for (int ni = 0; ni < 4; ni++) { cp0[ni] = 0.f; cp1[ni] = 0.f; }

#pragma unroll
    for (int ni = 0; ni < 4; ni++) {
        int gn = nBase + wn * 32 + ni * 8 + (lane & 3) * 2;
        bool ok = (gn < KK);   // gn even, KK even => gn+1 < KK as well
#pragma unroll
        for (int mi = 0; mi < 4; mi++) {
            int gm = mBase + wm * 64 + mi * 16 + (lane >> 2);
            float a0 = acc[mi][ni][0], a1 = acc[mi][ni][1];
            float a2 = acc[mi][ni][2], a3 = acc[mi][ni][3];
            float e0 = ex2f(a0 * C_EXP20), e1 = ex2f(a1 * C_EXP20);
            float e2 = ex2f(a2 * C_EXP20), e3 = ex2f(a3 * C_EXP20);
            if (ok) {
                __nv_bfloat162 eh0 = __floats2bfloat162_rn(e0, e1);
                __nv_bfloat162 eh1 = __floats2bfloat162_rn(e2, e3);
                __nv_bfloat162 ph0 = __floats2bfloat162_rn(a0, a1);
                __nv_bfloat162 ph1 = __floats2bfloat162_rn(a2, a3);
                *(uint32_t*)&g_E[(size_t)gm * KK + gn]       = *(uint32_t*)&eh0;
                *(uint32_t*)&g_E[(size_t)(gm + 8) * KK + gn] = *(uint32_t*)&eh1;
                *(uint32_t*)&g_P[(size_t)gm * KK + gn]       = *(uint32_t*)&ph0;
                *(uint32_t*)&g_P[(size_t)(gm + 8) * KK + gn] = *(uint32_t*)&ph1;
                cp0[ni] += e0 + e2;
                cp1[ni] += e1 + e3;
            }
        }
    }
#pragma unroll
    for (int ni = 0; ni < 4; ni++) {
#pragma unroll
        for (int o = 4; o < 32; o <<= 1) {
            cp0[ni] += __shfl_xor_sync(0xffffffffu, cp0[ni], o);
            cp1[ni] += __shfl_xor_sync(0xffffffffu, cp1[ni], o);
        }
        if (lane < 4) {
            cs[wm * 128 + wn * 32 + ni * 8 + lane * 2]     = cp0[ni];
            cs[wm * 128 + wn * 32 + ni * 8 + lane * 2 + 1] = cp1[ni];
        }
    }
    __syncthreads();
    if (tid < 128) {
        int mtile = (int)(blockIdx.x / nTilesN);
        g_partW[(size_t)mtile * KPAD + nBase + tid] = cs[tid] + cs[128 + tid];
    }
}

// ---------------- 3) W reductions --------------------------------------------
__global__ void reduce_w_epi_kernel(int halfStart) {   // sum 128 GEMM mtile slabs
    int k4 = (blockIdx.x * blockDim.x + threadIdx.x) * 4;
    if (k4 >= KK) return;
    const float* base = g_partW + (size_t)halfStart * KPAD + k4;
    float4 s = make_float4(0.f, 0.f, 0.f, 0.f);
#pragma unroll 8
    for (int i = 0; i < 128; i++) {
        float4 p = *(const float4*)(base + (size_t)i * KPAD);
        s.x += p.x; s.y += p.y; s.z += p.z; s.w += p.w;
    }
    *(float4*)(g_W + k4) = s;
}

__global__ void reduce_w_fused_kernel() {              // sum NFB fused-block slabs
    int k4 = (blockIdx.x * blockDim.x + threadIdx.x) * 4;
    if (k4 >= KK) return;
    const float* base = g_part2 + k4;
    float4 s = make_float4(0.f, 0.f, 0.f, 0.f);
#pragma unroll 8
    for (int i = 0; i < NFB; i++) {
        float4 p = *(const float4*)(base + (size_t)i * KPAD);
        s.x += p.x; s.y += p.y; s.z += p.z; s.w += p.w;
    }
    *(float4*)(g_W + k4) = s;
}

__global__ void zreduce_kernel() {
    __shared__ float red[1024];
    float a = 0.0f;
    for (int k = threadIdx.x; k < KK; k += 1024) a += g_W[k];
    float z = blk_reduce_sum(a, red);
    if (threadIdx.x == 0) g_Z = z;
}

__global__ void compute_u_kernel() {
    int k = blockIdx.x * blockDim.x + threadIdx.x;
    if (k >= KK) return;
    float u = g_Z / ((float)KK * g_W[k]);
    g_u[k] = u;
    g_logu[k] = logf(u);
}

// ---------------- 4) fused row-normalize + column-sum pass -------------------
// Block owns RPB rows. Computes u inline from (W, Z); per 8-row round:
// warp-per-row rowsum -> v_r, then all threads accumulate v_r*E into column acc.
__global__ __launch_bounds__(256) void fused_rc_kernel(int simOff) {
    __shared__ float su[KPAD];
    __shared__ float sv[8];
    int tid = threadIdx.x, lane = tid & 31, wid = tid >> 5;
    float Z = g_Z;
    for (int i = tid; i < KK; i += 256) su[i] = Z / ((float)KK * g_W[i]);
    __syncthreads();

    float accx[6], accy[6];
#pragma unroll
    for (int i = 0; i < 6; i++) { accx[i] = 0.f; accy[i] = 0.f; }
    int rbase = (int)blockIdx.x * RPB;

    for (int j = 0; j < RPB / 8; j++) {
        // phase 1: warp `wid` -> rowsum of row rbase+j*8+wid
        const __nv_bfloat16* row = g_E + (size_t)(simOff + rbase + j * 8 + wid) * KK;
        float m = 0.f;
        for (int i = lane; i < KK / 8; i += 32) {
            uint4 raw = *(const uint4*)(row + i * 8);
            const __nv_bfloat162* h = (const __nv_bfloat162*)&raw;
            float4 u0 = *(const float4*)&su[i * 8];
            float4 u1 = *(const float4*)&su[i * 8 + 4];
            float2 e0 = __bfloat1622float2(h[0]);
            float2 e1 = __bfloat1622float2(h[1]);
            float2 e2 = __bfloat1622float2(h[2]);
            float2 e3 = __bfloat1622float2(h[3]);
            m += e0.x * u0.x + e0.y * u0.y + e1.x * u0.z + e1.y * u0.w
               + e2.x * u1.x + e2.y * u1.y + e3.x * u1.z + e3.y * u1.w;
        }
#pragma unroll
        for (int o = 16; o > 0; o >>= 1) m += __shfl_xor_sync(0xffffffffu, m, o);
        if (lane == 0) sv[wid] = Z / ((float)BB * m);
        __syncthreads();

        // phase 2: accumulate v_r * E into column partials (L1-hot re-read)
#pragma unroll
        for (int rr = 0; rr < 8; rr++) {
            float vv = sv[rr];
            const __nv_bfloat16* row2 = g_E + (size_t)(simOff + rbase + j * 8 + rr) * KK;
#pragma unroll
            for (int i = 0; i < 6; i++) {
                int c = 2 * tid + 512 * i;
                if (c < KK) {
                    uint32_t raw = *(const uint32_t*)(row2 + c);
                    float2 e = __bfloat1622float2(*(__nv_bfloat162*)&raw);
                    accx[i] += vv * e.x;
                    accy[i] += vv * e.y;
                }
            }
        }
        __syncthreads();
    }
#pragma unroll
    for (int i = 0; i < 6; i++) {
        int c = 2 * tid + 512 * i;
        if (c < KK)
            *(float2*)&g_part2[(size_t)blockIdx.x * KPAD + c] = make_float2(accx[i], accy[i]);
    }
}

// ---------------- 5) fused final ---------------------------------------------
__global__ void final_row_kernel(int simOff, int predOff) {
    __shared__ __nv_bfloat16 sE[KK];
    __shared__ __nv_bfloat16 sP[KK];
    __shared__ float red[256];
    int b = blockIdx.x, tid = threadIdx.x;
    {
        const uint4* pe = (const uint4*)(g_E + (size_t)(simOff + b) * KK);
        const uint4* pp = (const uint4*)(g_P + (size_t)(predOff + b) * KK);
        for (int i = tid; i < KK / 8; i += 256) {
            ((uint4*)sE)[i] = pe[i];
            ((uint4*)sP)[i] = pp[i];
        }
    }
    __syncthreads();

    float a = 0.0f;
    for (int k = tid; k < KK; k += 256) a += g_u[k] * __bfloat162float(sE[k]);
    float Mb = blk_reduce_sum(a, red);

    float mx = -1e30f;
    for (int k = tid; k < KK; k += 256) mx = fmaxf(mx, __bfloat162float(sP[k]));
    float m2 = C_EXP10 * blk_reduce_max(mx, red);
    float se = 0.0f;
    for (int k = tid; k < KK; k += 256)
        se += ex2f(__bfloat162float(sP[k]) * C_EXP10 - m2);
    float ssum = blk_reduce_sum(se, red);
    float lse_nat = C_LN2 * (m2 + log2f(ssum));

    float invMb = 1.0f / Mb;
    float logMb = logf(Mb);
    float L = 0.0f;
    for (int k = tid; k < KK; k += 256) {
        float e = __bfloat162float(sE[k]);
        float code = g_u[k] * e * invMb;
        float logc = g_logu[k] + C_LN2 * lg2f(e) - logMb;
        float logp = 10.0f * __bfloat162float(sP[k]) - lse_nat;
        L += code * (logc - logp);
    }
    float Lb = blk_reduce_sum(L, red);
    if (tid == 0) g_rowloss[b] = Lb;
}

__global__ void loss_reduce_kernel(int lossIdx) {
    __shared__ float red[1024];
    float a = 0.0f;
    for (int b = threadIdx.x; b < BB; b += 1024) a += g_rowloss[b];
    float s = blk_reduce_sum(a, red);
    if (threadIdx.x == 0) g_loss[lossIdx] = s / (float)BB;
}

__global__ void combine_kernel(float* out) {
    out[0] = 0.5f * (g_loss[0] + g_loss[1]);
}

// ---------------- launch ------------------------------------------------------
extern "C" void kernel_launch(void* const* d_in, const int* in_sizes, int n_in,
                              void* d_out, int out_size) {
    const float* q = (const float*)d_in[0];
    const float* k = (const float*)d_in[1];
    const float* c = (const float*)d_in[2];

    cudaFuncSetAttribute(gemm_mma_kernel, cudaFuncAttributeMaxDynamicSharedMemorySize,
                         GSTAGE * STAGE_BYTES);

    l2norm_bf16_kernel<<<BB / 8, 256>>>(q, BB, 0);
    l2norm_bf16_kernel<<<BB / 8, 256>>>(k, BB, 1);
    l2norm_bf16_kernel<<<(KK + 7) / 8, 256>>>(c, KK, 2);
    padc_kernel<<<(((KPAD - KK) * DD) + 255) / 256, 256>>>();

    gemm_mma_kernel<<<(2 * BB / 128) * (KPAD / 128), 256, GSTAGE * STAGE_BYTES>>>();

    for (int l = 0; l < 2; l++) {
        int halfStart = (l == 0) ? 128 : 0;   // mtile range of the sim half
        int simOff    = (l == 0) ? BB : 0;
        int predOff   = BB - simOff;

        reduce_w_epi_kernel<<<6, 128>>>(halfStart);   // W1 (from GEMM epilogue)
        zreduce_kernel<<<1, 1024>>>();                // Z (constant across iters)
        fused_rc_kernel<<<NFB, 256>>>(simOff);        // u1 inline; v1; W2 partials
        reduce_w_fused_kernel<<<6, 128>>>();          // W2
        fused_rc_kernel<<<NFB, 256>>>(simOff);        // u2 inline; v2; W3 partials
        reduce_w_fused_kernel<<<6, 128>>>();          // W3
        compute_u_kernel<<<(KK + 127) / 128, 128>>>();// u3, log u3
        final_row_kernel<<<BB, 256>>>(simOff, predOff);
        loss_reduce_kernel<<<1, 1024>>>(l);
    }
    combine_kernel<<<1, 1>>>((float*)d_out);
}

// round 8
// speedup vs baseline: 3.7475x; 1.5060x over previous
#include <cuda_runtime.h>
#include <cuda_bf16.h>
#include <cstdint>

#define BB 16384
#define DD 256
#define KK 3000
#define KPAD 3072
#define NFB2 1024        // fused row/col blocks over ALL 2B rows
#define RPB 32           // rows per fused block
#define RFB 8            // rows per final block

#define C_EXP20 28.853900817779268f   // 20/ln2
#define C_EXP10 14.426950408889634f   // 10/ln2
#define C_LN2   0.6931471805599453f

// ---------------- device scratch -------------------------------------------
__device__ __align__(16) __nv_bfloat16 g_A2[(size_t)2 * BB * DD];
__device__ __align__(16) __nv_bfloat16 g_B2[(size_t)KPAD * DD];
__device__ __align__(16) __nv_bfloat16 g_E[(size_t)2 * BB * KK];  // exp(sim/eps) bf16
__device__ __align__(16) __nv_bfloat16 g_P[(size_t)2 * BB * KK];  // sim bf16
__device__ float g_partW[(size_t)256 * KPAD];    // per-GEMM-mtile col partials of E
__device__ float g_part2[(size_t)NFB2 * KPAD];   // fused-pass col partials
__device__ float g_W[2 * KPAD];
__device__ float2 g_ul[2 * KK];                  // (u, log u) per loss
__device__ float g_Z[2];
__device__ float g_rowloss[2 * BB];

// ---------------- helpers ----------------------------------------------------
static __device__ __forceinline__ float ex2f(float x) {
    float y; asm("ex2.approx.ftz.f32 %0, %1;" : "=f"(y) : "f"(x)); return y;
}
static __device__ __forceinline__ float lg2f(float x) {
    float y; asm("lg2.approx.ftz.f32 %0, %1;" : "=f"(y) : "f"(x)); return y;
}
static __device__ __forceinline__ uint32_t s2u(const void* p) {
    uint32_t a;
    asm("{ .reg .u64 t; cvta.to.shared.u64 t, %1; cvt.u32.u64 %0, t; }" : "=r"(a) : "l"(p));
    return a;
}

#define LDSM4(r, a)                                                             \
    asm volatile("ldmatrix.sync.aligned.m8n8.x4.shared.b16 {%0,%1,%2,%3}, [%4];" \
                 : "=r"((r)[0]), "=r"((r)[1]), "=r"((r)[2]), "=r"((r)[3]) : "r"(a))

#define MMA16816(d, a, b)                                                       \
    asm volatile(                                                               \
        "mma.sync.aligned.m16n8k16.row.col.f32.bf16.bf16.f32 "                  \
        "{%0,%1,%2,%3}, {%4,%5,%6,%7}, {%8,%9}, {%0,%1,%2,%3};"                 \
        : "+f"((d)[0]), "+f"((d)[1]), "+f"((d)[2]), "+f"((d)[3])                \
        : "r"((a)[0]), "r"((a)[1]), "r"((a)[2]), "r"((a)[3]),                   \
          "r"((b)[0]), "r"((b)[1]))

#define CPASYNC16(dst, src) \
    asm volatile("cp.async.cg.shared.global [%0], [%1], 16;" :: "r"(dst), "l"(src))

// ---------------- 1) L2 normalize (q,k,c) + pad, one launch ------------------
__global__ void l2norm_all_kernel(const float* __restrict__ q,
                                  const float* __restrict__ k,
                                  const float* __restrict__ c) {
    int row  = blockIdx.x * 8 + (threadIdx.x >> 5);
    int lane = threadIdx.x & 31;
    if (row >= 2 * BB + KPAD) return;

    const float* src;
    __nv_bfloat16* dst;
    if (row < BB)            { src = q + (size_t)row * DD;            dst = g_A2 + (size_t)row * DD; }
    else if (row < 2 * BB)   { src = k + (size_t)(row - BB) * DD;     dst = g_A2 + (size_t)row * DD; }
    else if (row < 2 * BB + KK) { src = c + (size_t)(row - 2 * BB) * DD; dst = g_B2 + (size_t)(row - 2 * BB) * DD; }
    else {   // zero-pad rows KK..KPAD of B
        dst = g_B2 + (size_t)(row - 2 * BB) * DD;
#pragma unroll
        for (int i = 0; i < 8; i++) dst[lane + 32 * i] = __float2bfloat16(0.0f);
        return;
    }
    float v[8]; float s = 0.0f;
#pragma unroll
    for (int i = 0; i < 8; i++) { v[i] = src[lane + 32 * i]; s += v[i] * v[i]; }
#pragma unroll
    for (int o = 16; o > 0; o >>= 1) s += __shfl_xor_sync(0xffffffffu, s, o);
    float inv = 1.0f / fmaxf(sqrtf(s), 1e-12f);
#pragma unroll
    for (int i = 0; i < 8; i++) dst[lane + 32 * i] = __float2bfloat16(v[i] * inv);
}

// ---------------- 2) GEMM + fused epilogue (E, P, W1-partials) ---------------
#define GSTAGE 3
#define STAGE_BYTES 32768
#define NIT (DD / 64)

__global__ __launch_bounds__(256) void gemm_mma_kernel() {
    extern __shared__ char smem[];
    const uint32_t sb = s2u(smem);
    const int tid = threadIdx.x;
    const int lane = tid & 31;
    const int wid = tid >> 5;
    const int wm = wid >> 2;
    const int wn = wid & 3;

    const int nTilesN = KPAD / 128;   // 24
    const int mBase = (int)(blockIdx.x / nTilesN) * 128;
    const int nBase = (int)(blockIdx.x % nTilesN) * 128;

    const __nv_bfloat16* gA = g_A2 + (size_t)mBase * DD;
    const __nv_bfloat16* gB = g_B2 + (size_t)nBase * DD;

    float acc[4][4][4] = {};

    auto load_stage = [&](int s, int kIter) {
        uint32_t so = sb + (uint32_t)s * STAGE_BYTES;
        int k0 = kIter * 64;
#pragma unroll
        for (int i = 0; i < 4; i++) {
            int q = tid * 4 + i;
            int row = q >> 3;
            int c = q & 7;
            uint32_t dst = so + row * 128 + ((c ^ (row & 7)) << 4);
            CPASYNC16(dst, gA + (size_t)row * DD + k0 + c * 8);
            CPASYNC16(dst + 16384, gB + (size_t)row * DD + k0 + c * 8);
        }
        asm volatile("cp.async.commit_group;" ::: "memory");
    };

    load_stage(0, 0);
    load_stage(1, 1);

    for (int it = 0; it < NIT; it++) {
        if (it + 2 < NIT) asm volatile("cp.async.wait_group 1;" ::: "memory");
        else              asm volatile("cp.async.wait_group 0;" ::: "memory");
        __syncthreads();
        if (it + 2 < NIT) load_stage((it + 2) % GSTAGE, it + 2);

        uint32_t aB = sb + (uint32_t)(it % GSTAGE) * STAGE_BYTES;
        uint32_t bB = aB + 16384;
#pragma unroll
        for (int ks = 0; ks < 4; ks++) {
            uint32_t a[4][4], b[4][2];
            int cch = ks * 2 + (lane >> 4);
#pragma unroll
            for (int mi = 0; mi < 4; mi++) {
                int row = wm * 64 + mi * 16 + (lane & 15);
                uint32_t addr = aB + row * 128 + ((cch ^ (row & 7)) << 4);
                LDSM4(a[mi], addr);
            }
#pragma unroll
            for (int nj = 0; nj < 2; nj++) {
                int row = wn * 32 + nj * 16 + (lane & 15);
                uint32_t addr = bB + row * 128 + ((cch ^ (row & 7)) << 4);
                uint32_t r4[4];
                LDSM4(r4, addr);
                b[nj * 2][0]     = r4[0]; b[nj * 2][1]     = r4[2];
                b[nj * 2 + 1][0] = r4[1]; b[nj * 2 + 1][1] = r4[3];
            }
#pragma unroll
            for (int mi = 0; mi < 4; mi++)
#pragma unroll
                for (int ni = 0; ni < 4; ni++)
                    MMA16816(acc[mi][ni], a[mi], b[ni]);
        }
        __syncthreads();
    }

    // fused epilogue: E bf16, P bf16, per-tile column sums of E
    float* cs = (float*)smem;
    float cp0[4], cp1[4];
#pragma unroll
    for (int ni = 0; ni < 4; ni++) { cp0[ni] = 0.f; cp1[ni] = 0.f; }

#pragma unroll
    for (int ni = 0; ni < 4; ni++) {
        int gn = nBase + wn * 32 + ni * 8 + (lane & 3) * 2;
        bool ok = (gn < KK);
#pragma unroll
        for (int mi = 0; mi < 4; mi++) {
            int gm = mBase + wm * 64 + mi * 16 + (lane >> 2);
            float a0 = acc[mi][ni][0], a1 = acc[mi][ni][1];
            float a2 = acc[mi][ni][2], a3 = acc[mi][ni][3];
            float e0 = ex2f(a0 * C_EXP20), e1 = ex2f(a1 * C_EXP20);
            float e2 = ex2f(a2 * C_EXP20), e3 = ex2f(a3 * C_EXP20);
            if (ok) {
                __nv_bfloat162 eh0 = __floats2bfloat162_rn(e0, e1);
                __nv_bfloat162 eh1 = __floats2bfloat162_rn(e2, e3);
                __nv_bfloat162 ph0 = __floats2bfloat162_rn(a0, a1);
                __nv_bfloat162 ph1 = __floats2bfloat162_rn(a2, a3);
                *(uint32_t*)&g_E[(size_t)gm * KK + gn]       = *(uint32_t*)&eh0;
                *(uint32_t*)&g_E[(size_t)(gm + 8) * KK + gn] = *(uint32_t*)&eh1;
                *(uint32_t*)&g_P[(size_t)gm * KK + gn]       = *(uint32_t*)&ph0;
                *(uint32_t*)&g_P[(size_t)(gm + 8) * KK + gn] = *(uint32_t*)&ph1;
                cp0[ni] += e0 + e2;
                cp1[ni] += e1 + e3;
            }
        }
    }
#pragma unroll
    for (int ni = 0; ni < 4; ni++) {
#pragma unroll
        for (int o = 4; o < 32; o <<= 1) {
            cp0[ni] += __shfl_xor_sync(0xffffffffu, cp0[ni], o);
            cp1[ni] += __shfl_xor_sync(0xffffffffu, cp1[ni], o);
        }
        if (lane < 4) {
            cs[wm * 128 + wn * 32 + ni * 8 + lane * 2]     = cp0[ni];
            cs[wm * 128 + wn * 32 + ni * 8 + lane * 2 + 1] = cp1[ni];
        }
    }
    __syncthreads();
    if (tid < 128) {
        int mtile = (int)(blockIdx.x / nTilesN);
        g_partW[(size_t)mtile * KPAD + nBase + tid] = cs[tid] + cs[128 + tid];
    }
}

// ---------------- 3) slab reductions (both losses, 2D blocks) ----------------
__global__ void reduce_w_epi_kernel() {   // grid (6,2), block (128,4)
    int l = blockIdx.y;
    int halfStart = (l == 0) ? 128 : 0;
    int tx = threadIdx.x, ty = threadIdx.y;
    int k4 = (blockIdx.x * 128 + tx) * 4;
    __shared__ float4 sm[4][128];
    float4 s = make_float4(0.f, 0.f, 0.f, 0.f);
    if (k4 < KK) {
        const float* base = g_partW + (size_t)(halfStart + ty * 32) * KPAD + k4;
#pragma unroll 8
        for (int i = 0; i < 32; i++) {
            float4 p = *(const float4*)(base + (size_t)i * KPAD);
            s.x += p.x; s.y += p.y; s.z += p.z; s.w += p.w;
        }
    }
    sm[ty][tx] = s;
    __syncthreads();
    if (ty == 0 && k4 < KK) {
#pragma unroll
        for (int w = 1; w < 4; w++) {
            float4 p = sm[w][tx];
            s.x += p.x; s.y += p.y; s.z += p.z; s.w += p.w;
        }
        *(float4*)&g_W[l * KPAD + k4] = s;
    }
}

__global__ void reduce_w_fused_kernel() {   // grid (6,2), block (128,8)
    int l = blockIdx.y;
    int slabStart = (l == 0) ? 512 : 0;   // rows >= BB are sim of loss 0
    int tx = threadIdx.x, ty = threadIdx.y;
    int k4 = (blockIdx.x * 128 + tx) * 4;
    __shared__ float4 sm[8][128];
    float4 s = make_float4(0.f, 0.f, 0.f, 0.f);
    if (k4 < KK) {
        const float* base = g_part2 + (size_t)(slabStart + ty * 64) * KPAD + k4;
#pragma unroll 8
        for (int i = 0; i < 64; i++) {
            float4 p = *(const float4*)(base + (size_t)i * KPAD);
            s.x += p.x; s.y += p.y; s.z += p.z; s.w += p.w;
        }
    }
    sm[ty][tx] = s;
    __syncthreads();
    if (ty == 0 && k4 < KK) {
#pragma unroll
        for (int w = 1; w < 8; w++) {
            float4 p = sm[w][tx];
            s.x += p.x; s.y += p.y; s.z += p.z; s.w += p.w;
        }
        *(float4*)&g_W[l * KPAD + k4] = s;
    }
}

__global__ void zreduce_kernel() {   // grid 2
    __shared__ float red[1024];
    int l = blockIdx.x, tid = threadIdx.x;
    float a = 0.0f;
    for (int k = tid; k < KK; k += 1024) a += g_W[l * KPAD + k];
    red[tid] = a; __syncthreads();
    for (int s = 512; s > 0; s >>= 1) {
        if (tid < s) red[tid] += red[tid + s];
        __syncthreads();
    }
    if (tid == 0) g_Z[l] = red[0];
}

__global__ void compute_u_kernel() {   // grid (24,2), block 128
    int l = blockIdx.y;
    int k = blockIdx.x * 128 + threadIdx.x;
    if (k >= KK) return;
    float u = g_Z[l] / ((float)KK * g_W[l * KPAD + k]);
    g_ul[l * KK + k] = make_float2(u, logf(u));
}

// ---------------- 4) fused row-normalize + column-sum (all 2B rows) ----------
__global__ __launch_bounds__(256) void fused_rc_kernel() {
    __shared__ float su[KPAD];
    __shared__ float sv[8];
    int tid = threadIdx.x, lane = tid & 31, wid = tid >> 5;
    int rbase = (int)blockIdx.x * RPB;          // global row in E
    int l = (rbase >= BB) ? 0 : 1;
    const float* W = g_W + (size_t)l * KPAD;
    float Z = g_Z[l];
    for (int i = tid; i < KK; i += 256) su[i] = Z / ((float)KK * W[i]);
    __syncthreads();

    float accx[6], accy[6];
#pragma unroll
    for (int i = 0; i < 6; i++) { accx[i] = 0.f; accy[i] = 0.f; }

    for (int j = 0; j < RPB / 8; j++) {
        const __nv_bfloat16* row = g_E + (size_t)(rbase + j * 8 + wid) * KK;
        float m = 0.f;
        for (int i = lane; i < KK / 8; i += 32) {
            uint4 raw = *(const uint4*)(row + i * 8);
            const __nv_bfloat162* h = (const __nv_bfloat162*)&raw;
            float4 u0 = *(const float4*)&su[i * 8];
            float4 u1 = *(const float4*)&su[i * 8 + 4];
            float2 e0 = __bfloat1622float2(h[0]);
            float2 e1 = __bfloat1622float2(h[1]);
            float2 e2 = __bfloat1622float2(h[2]);
            float2 e3 = __bfloat1622float2(h[3]);
            m += e0.x * u0.x + e0.y * u0.y + e1.x * u0.z + e1.y * u0.w
               + e2.x * u1.x + e2.y * u1.y + e3.x * u1.z + e3.y * u1.w;
        }
#pragma unroll
        for (int o = 16; o > 0; o >>= 1) m += __shfl_xor_sync(0xffffffffu, m, o);
        if (lane == 0) sv[wid] = Z / ((float)BB * m);
        __syncthreads();

#pragma unroll
        for (int rr = 0; rr < 8; rr++) {
            float vv = sv[rr];
            const __nv_bfloat16* row2 = g_E + (size_t)(rbase + j * 8 + rr) * KK;
#pragma unroll
            for (int i = 0; i < 6; i++) {
                int c = 2 * tid + 512 * i;
                if (c < KK) {
                    uint32_t raw = *(const uint32_t*)(row2 + c);
                    float2 e = __bfloat1622float2(*(__nv_bfloat162*)&raw);
                    accx[i] += vv * e.x;
                    accy[i] += vv * e.y;
                }
            }
        }
        __syncthreads();
    }
#pragma unroll
    for (int i = 0; i < 6; i++) {
        int c = 2 * tid + 512 * i;
        if (c < KK)
            *(float2*)&g_part2[(size_t)blockIdx.x * KPAD + c] = make_float2(accx[i], accy[i]);
    }
}

// ---------------- 5) final: 8 rows per block, u cached in registers ----------
__global__ __launch_bounds__(256) void final_row_kernel() {
    __shared__ __nv_bfloat16 sE[KK];
    __shared__ __nv_bfloat16 sP[KK];
    __shared__ float red[16];
    int tid = threadIdx.x, lane = tid & 31, wid = tid >> 5;
    int r0 = (int)blockIdx.x * RFB;        // loss-row id 0..32767 (block's rows share loss)
    int l = r0 >> 14;
    int simBase  = (l == 0) ? BB : 0;
    int predBase = BB - simBase;

    // preload (u, log u) pairs for this thread's k-slots into registers
    float4 uu[6];
    const float4* ulp = (const float4*)(g_ul + (size_t)l * KK);
#pragma unroll
    for (int i = 0; i < 6; i++) {
        int p2 = tid + 256 * i;
        uu[i] = (p2 < KK / 2) ? ulp[p2] : make_float4(0.f, 0.f, 0.f, 0.f);
    }
    const float M2 = C_EXP10;   // pred/T <= 10 (cosine), fixed lse shift

    for (int j = 0; j < RFB; j++) {
        int rr = (r0 + j) & (BB - 1);
        const uint4* pe = (const uint4*)(g_E + (size_t)(simBase + rr) * KK);
        const uint4* pp = (const uint4*)(g_P + (size_t)(predBase + rr) * KK);
        for (int i = tid; i < KK / 8; i += 256) {
            ((uint4*)sE)[i] = pe[i];
            ((uint4*)sP)[i] = pp[i];
        }
        __syncthreads();

        // pass 1: Mb and lse-sum together
        float a = 0.f, se = 0.f;
#pragma unroll
        for (int i = 0; i < 6; i++) {
            int p2 = tid + 256 * i;
            if (p2 < KK / 2) {
                float2 e = __bfloat1622float2(((const __nv_bfloat162*)sE)[p2]);
                float2 p = __bfloat1622float2(((const __nv_bfloat162*)sP)[p2]);
                a  += uu[i].x * e.x + uu[i].z * e.y;
                se += ex2f(fmaf(p.x, C_EXP10, -M2)) + ex2f(fmaf(p.y, C_EXP10, -M2));
            }
        }
#pragma unroll
        for (int o = 16; o > 0; o >>= 1) {
            a  += __shfl_xor_sync(0xffffffffu, a, o);
            se += __shfl_xor_sync(0xffffffffu, se, o);
        }
        if (lane == 0) { red[wid] = a; red[8 + wid] = se; }
        __syncthreads();
        float Mb = 0.f, ses = 0.f;
#pragma unroll
        for (int w = 0; w < 8; w++) { Mb += red[w]; ses += red[8 + w]; }

        float lse = C_LN2 * (M2 + log2f(ses));
        float invMb = 1.0f / Mb;
        float logMb = logf(Mb);

        // pass 2: KL accumulation
        float L = 0.f;
#pragma unroll
        for (int i = 0; i < 6; i++) {
            int p2 = tid + 256 * i;
            if (p2 < KK / 2) {
                float2 e = __bfloat1622float2(((const __nv_bfloat162*)sE)[p2]);
                float2 p = __bfloat1622float2(((const __nv_bfloat162*)sP)[p2]);
                float t0 = uu[i].y + C_LN2 * lg2f(e.x) - logMb - 10.0f * p.x + lse;
                float t1 = uu[i].w + C_LN2 * lg2f(e.y) - logMb - 10.0f * p.y + lse;
                L += uu[i].x * e.x * t0 + uu[i].z * e.y * t1;
            }
        }
#pragma unroll
        for (int o = 16; o > 0; o >>= 1) L += __shfl_xor_sync(0xffffffffu, L, o);
        __syncthreads();               // protect red reuse
        if (lane == 0) red[wid] = L;
        __syncthreads();
        if (tid == 0) {
            float Ls = 0.f;
#pragma unroll
            for (int w = 0; w < 8; w++) Ls += red[w];
            g_rowloss[r0 + j] = Ls * invMb;
        }
        __syncthreads();               // before next row overwrites sE/sP
    }
}

__global__ void loss_reduce_kernel(float* out) {
    __shared__ float red[1024];
    int tid = threadIdx.x;
    float a = 0.0f;
    for (int b = tid; b < 2 * BB; b += 1024) a += g_rowloss[b];
    red[tid] = a; __syncthreads();
    for (int s = 512; s > 0; s >>= 1) {
        if (tid < s) red[tid] += red[tid + s];
        __syncthreads();
    }
    if (tid == 0) out[0] = red[0] / (float)(2 * BB);
}

// ---------------- launch ------------------------------------------------------
extern "C" void kernel_launch(void* const* d_in, const int* in_sizes, int n_in,
                              void* d_out, int out_size) {
    const float* q = (const float*)d_in[0];
    const float* k = (const float*)d_in[1];
    const float* c = (const float*)d_in[2];

    cudaFuncSetAttribute(gemm_mma_kernel, cudaFuncAttributeMaxDynamicSharedMemorySize,
                         GSTAGE * STAGE_BYTES);

    l2norm_all_kernel<<<(2 * BB + KPAD) / 8, 256>>>(q, k, c);
    gemm_mma_kernel<<<(2 * BB / 128) * (KPAD / 128), 256, GSTAGE * STAGE_BYTES>>>();

    reduce_w_epi_kernel<<<dim3(6, 2), dim3(128, 4)>>>();    // W1 both losses
    zreduce_kernel<<<2, 1024>>>();                          // Z both losses
    fused_rc_kernel<<<NFB2, 256>>>();                       // u1 inline; v1; W2 partials
    reduce_w_fused_kernel<<<dim3(6, 2), dim3(128, 8)>>>();  // W2
    fused_rc_kernel<<<NFB2, 256>>>();                       // u2 inline; v2; W3 partials
    reduce_w_fused_kernel<<<dim3(6, 2), dim3(128, 8)>>>();  // W3
    compute_u_kernel<<<dim3(24, 2), 128>>>();               // u3, log u3
    final_row_kernel<<<2 * BB / RFB, 256>>>();              // both losses
    loss_reduce_kernel<<<1, 1024>>>((float*)d_out);
}

// round 9
// speedup vs baseline: 4.0783x; 1.0883x over previous
#include <cuda_runtime.h>
#include <cuda_bf16.h>
#include <cstdint>

#define BB 16384
#define DD 256
#define KK 3000
#define KPAD 3072
#define NFB2 1024        // fused row/col blocks over ALL 2B rows
#define RPB 32           // rows per fused block
#define RFB 8            // row-pairs per final block

#define C_EXP20 28.853900817779268f   // 20/ln2
#define C_EXP10 14.426950408889634f   // 10/ln2
#define C_LN2   0.6931471805599453f

// ---------------- device scratch -------------------------------------------
__device__ __align__(16) __nv_bfloat16 g_A2[(size_t)2 * BB * DD];
__device__ __align__(16) __nv_bfloat16 g_B2[(size_t)KPAD * DD];
__device__ __align__(16) __nv_bfloat16 g_E[(size_t)2 * BB * KK];  // exp(sim/eps) bf16
__device__ float g_partW[(size_t)256 * KPAD];    // per-GEMM-mtile col partials of E
__device__ float g_part2[(size_t)NFB2 * KPAD];   // fused-pass col partials
__device__ float g_W[2 * KPAD];
__device__ float2 g_ul[2 * KK];                  // (u, log u) per loss
__device__ float g_Z[2];
__device__ float g_rowloss[BB];

// ---------------- helpers ----------------------------------------------------
static __device__ __forceinline__ float ex2f(float x) {
    float y; asm("ex2.approx.ftz.f32 %0, %1;" : "=f"(y) : "f"(x)); return y;
}
static __device__ __forceinline__ float lg2f(float x) {
    float y; asm("lg2.approx.ftz.f32 %0, %1;" : "=f"(y) : "f"(x)); return y;
}
static __device__ __forceinline__ uint32_t s2u(const void* p) {
    uint32_t a;
    asm("{ .reg .u64 t; cvta.to.shared.u64 t, %1; cvt.u32.u64 %0, t; }" : "=r"(a) : "l"(p));
    return a;
}

#define LDSM4(r, a)                                                             \
    asm volatile("ldmatrix.sync.aligned.m8n8.x4.shared.b16 {%0,%1,%2,%3}, [%4];" \
                 : "=r"((r)[0]), "=r"((r)[1]), "=r"((r)[2]), "=r"((r)[3]) : "r"(a))

#define MMA16816(d, a, b)                                                       \
    asm volatile(                                                               \
        "mma.sync.aligned.m16n8k16.row.col.f32.bf16.bf16.f32 "                  \
        "{%0,%1,%2,%3}, {%4,%5,%6,%7}, {%8,%9}, {%0,%1,%2,%3};"                 \
        : "+f"((d)[0]), "+f"((d)[1]), "+f"((d)[2]), "+f"((d)[3])                \
        : "r"((a)[0]), "r"((a)[1]), "r"((a)[2]), "r"((a)[3]),                   \
          "r"((b)[0]), "r"((b)[1]))

#define CPASYNC16(dst, src) \
    asm volatile("cp.async.cg.shared.global [%0], [%1], 16;" :: "r"(dst), "l"(src))

// ---------------- 1) L2 normalize (q,k,c) + pad, one launch ------------------
__global__ void l2norm_all_kernel(const float* __restrict__ q,
                                  const float* __restrict__ k,
                                  const float* __restrict__ c) {
    int row  = blockIdx.x * 8 + (threadIdx.x >> 5);
    int lane = threadIdx.x & 31;
    if (row >= 2 * BB + KPAD) return;

    const float* src;
    __nv_bfloat16* dst;
    if (row < BB)            { src = q + (size_t)row * DD;            dst = g_A2 + (size_t)row * DD; }
    else if (row < 2 * BB)   { src = k + (size_t)(row - BB) * DD;     dst = g_A2 + (size_t)row * DD; }
    else if (row < 2 * BB + KK) { src = c + (size_t)(row - 2 * BB) * DD; dst = g_B2 + (size_t)(row - 2 * BB) * DD; }
    else {
        dst = g_B2 + (size_t)(row - 2 * BB) * DD;
#pragma unroll
        for (int i = 0; i < 8; i++) dst[lane + 32 * i] = __float2bfloat16(0.0f);
        return;
    }
    float v[8]; float s = 0.0f;
#pragma unroll
    for (int i = 0; i < 8; i++) { v[i] = src[lane + 32 * i]; s += v[i] * v[i]; }
#pragma unroll
    for (int o = 16; o > 0; o >>= 1) s += __shfl_xor_sync(0xffffffffu, s, o);
    float inv = 1.0f / fmaxf(sqrtf(s), 1e-12f);
#pragma unroll
    for (int i = 0; i < 8; i++) dst[lane + 32 * i] = __float2bfloat16(v[i] * inv);
}

// ---------------- 2) GEMM + fused epilogue (E, W1-partials) ------------------
#define GSTAGE 3
#define STAGE_BYTES 32768
#define NIT (DD / 64)

__global__ __launch_bounds__(256) void gemm_mma_kernel() {
    extern __shared__ char smem[];
    const uint32_t sb = s2u(smem);
    const int tid = threadIdx.x;
    const int lane = tid & 31;
    const int wid = tid >> 5;
    const int wm = wid >> 2;
    const int wn = wid & 3;

    const int nTilesN = KPAD / 128;   // 24
    const int mBase = (int)(blockIdx.x / nTilesN) * 128;
    const int nBase = (int)(blockIdx.x % nTilesN) * 128;

    const __nv_bfloat16* gA = g_A2 + (size_t)mBase * DD;
    const __nv_bfloat16* gB = g_B2 + (size_t)nBase * DD;

    float acc[4][4][4] = {};

    auto load_stage = [&](int s, int kIter) {
        uint32_t so = sb + (uint32_t)s * STAGE_BYTES;
        int k0 = kIter * 64;
#pragma unroll
        for (int i = 0; i < 4; i++) {
            int q = tid * 4 + i;
            int row = q >> 3;
            int c = q & 7;
            uint32_t dst = so + row * 128 + ((c ^ (row & 7)) << 4);
            CPASYNC16(dst, gA + (size_t)row * DD + k0 + c * 8);
            CPASYNC16(dst + 16384, gB + (size_t)row * DD + k0 + c * 8);
        }
        asm volatile("cp.async.commit_group;" ::: "memory");
    };

    load_stage(0, 0);
    load_stage(1, 1);

    for (int it = 0; it < NIT; it++) {
        if (it + 2 < NIT) asm volatile("cp.async.wait_group 1;" ::: "memory");
        else              asm volatile("cp.async.wait_group 0;" ::: "memory");
        __syncthreads();
        if (it + 2 < NIT) load_stage((it + 2) % GSTAGE, it + 2);

        uint32_t aB = sb + (uint32_t)(it % GSTAGE) * STAGE_BYTES;
        uint32_t bB = aB + 16384;
#pragma unroll
        for (int ks = 0; ks < 4; ks++) {
            uint32_t a[4][4], b[4][2];
            int cch = ks * 2 + (lane >> 4);
#pragma unroll
            for (int mi = 0; mi < 4; mi++) {
                int row = wm * 64 + mi * 16 + (lane & 15);
                uint32_t addr = aB + row * 128 + ((cch ^ (row & 7)) << 4);
                LDSM4(a[mi], addr);
            }
#pragma unroll
            for (int nj = 0; nj < 2; nj++) {
                int row = wn * 32 + nj * 16 + (lane & 15);
                uint32_t addr = bB + row * 128 + ((cch ^ (row & 7)) << 4);
                uint32_t r4[4];
                LDSM4(r4, addr);
                b[nj * 2][0]     = r4[0]; b[nj * 2][1]     = r4[2];
                b[nj * 2 + 1][0] = r4[1]; b[nj * 2 + 1][1] = r4[3];
            }
#pragma unroll
            for (int mi = 0; mi < 4; mi++)
#pragma unroll
                for (int ni = 0; ni < 4; ni++)
                    MMA16816(acc[mi][ni], a[mi], b[ni]);
        }
        __syncthreads();
    }

    // fused epilogue: E bf16 + per-tile column sums of E
    float* cs = (float*)smem;
    float cp0[4], cp1[4];
#pragma unroll
    for (int ni = 0; ni < 4; ni++) { cp0[ni] = 0.f; cp1[ni] = 0.f; }

#pragma unroll
    for (int ni = 0; ni < 4; ni++) {
        int gn = nBase + wn * 32 + ni * 8 + (lane & 3) * 2;
        bool ok = (gn < KK);
#pragma unroll
        for (int mi = 0; mi < 4; mi++) {
            int gm = mBase + wm * 64 + mi * 16 + (lane >> 2);
            float e0 = ex2f(acc[mi][ni][0] * C_EXP20), e1 = ex2f(acc[mi][ni][1] * C_EXP20);
            float e2 = ex2f(acc[mi][ni][2] * C_EXP20), e3 = ex2f(acc[mi][ni][3] * C_EXP20);
            if (ok) {
                __nv_bfloat162 eh0 = __floats2bfloat162_rn(e0, e1);
                __nv_bfloat162 eh1 = __floats2bfloat162_rn(e2, e3);
                *(uint32_t*)&g_E[(size_t)gm * KK + gn]       = *(uint32_t*)&eh0;
                *(uint32_t*)&g_E[(size_t)(gm + 8) * KK + gn] = *(uint32_t*)&eh1;
                cp0[ni] += e0 + e2;
                cp1[ni] += e1 + e3;
            }
        }
    }
#pragma unroll
    for (int ni = 0; ni < 4; ni++) {
#pragma unroll
        for (int o = 4; o < 32; o <<= 1) {
            cp0[ni] += __shfl_xor_sync(0xffffffffu, cp0[ni], o);
            cp1[ni] += __shfl_xor_sync(0xffffffffu, cp1[ni], o);
        }
        if (lane < 4) {
            cs[wm * 128 + wn * 32 + ni * 8 + lane * 2]     = cp0[ni];
            cs[wm * 128 + wn * 32 + ni * 8 + lane * 2 + 1] = cp1[ni];
        }
    }
    __syncthreads();
    if (tid < 128) {
        int mtile = (int)(blockIdx.x / nTilesN);
        g_partW[(size_t)mtile * KPAD + nBase + tid] = cs[tid] + cs[128 + tid];
    }
}

// ---------------- 3) slab reductions -----------------------------------------
__global__ void reduce_w_epi_kernel() {   // grid (6,2), block (128,4)
    int l = blockIdx.y;
    int halfStart = (l == 0) ? 128 : 0;
    int tx = threadIdx.x, ty = threadIdx.y;
    int k4 = (blockIdx.x * 128 + tx) * 4;
    __shared__ float4 sm[4][128];
    float4 s = make_float4(0.f, 0.f, 0.f, 0.f);
    if (k4 < KK) {
        const float* base = g_partW + (size_t)(halfStart + ty * 32) * KPAD + k4;
#pragma unroll 8
        for (int i = 0; i < 32; i++) {
            float4 p = *(const float4*)(base + (size_t)i * KPAD);
            s.x += p.x; s.y += p.y; s.z += p.z; s.w += p.w;
        }
    }
    sm[ty][tx] = s;
    __syncthreads();
    if (ty == 0 && k4 < KK) {
#pragma unroll
        for (int w = 1; w < 4; w++) {
            float4 p = sm[w][tx];
            s.x += p.x; s.y += p.y; s.z += p.z; s.w += p.w;
        }
        *(float4*)&g_W[l * KPAD + k4] = s;
    }
}

__global__ void reduce_w_fused_kernel(int writeU) {   // grid (6,2), block (128,8)
    int l = blockIdx.y;
    int slabStart = (l == 0) ? 512 : 0;
    int tx = threadIdx.x, ty = threadIdx.y;
    int k4 = (blockIdx.x * 128 + tx) * 4;
    __shared__ float4 sm[8][128];
    float4 s = make_float4(0.f, 0.f, 0.f, 0.f);
    if (k4 < KK) {
        const float* base = g_part2 + (size_t)(slabStart + ty * 64) * KPAD + k4;
#pragma unroll 8
        for (int i = 0; i < 64; i++) {
            float4 p = *(const float4*)(base + (size_t)i * KPAD);
            s.x += p.x; s.y += p.y; s.z += p.z; s.w += p.w;
        }
    }
    sm[ty][tx] = s;
    __syncthreads();
    if (ty == 0 && k4 < KK) {
#pragma unroll
        for (int w = 1; w < 8; w++) {
            float4 p = sm[w][tx];
            s.x += p.x; s.y += p.y; s.z += p.z; s.w += p.w;
        }
        *(float4*)&g_W[l * KPAD + k4] = s;
        if (writeU) {
            float Z = g_Z[l];
            float u0 = Z / ((float)KK * s.x), u1 = Z / ((float)KK * s.y);
            float u2 = Z / ((float)KK * s.z), u3 = Z / ((float)KK * s.w);
            g_ul[l * KK + k4]     = make_float2(u0, logf(u0));
            g_ul[l * KK + k4 + 1] = make_float2(u1, logf(u1));
            g_ul[l * KK + k4 + 2] = make_float2(u2, logf(u2));
            g_ul[l * KK + k4 + 3] = make_float2(u3, logf(u3));
        }
    }
}

__global__ void zreduce_kernel() {   // grid 2
    __shared__ float red[1024];
    int l = blockIdx.x, tid = threadIdx.x;
    float a = 0.0f;
    for (int k = tid; k < KK; k += 1024) a += g_W[l * KPAD + k];
    red[tid] = a; __syncthreads();
    for (int s = 512; s > 0; s >>= 1) {
        if (tid < s) red[tid] += red[tid + s];
        __syncthreads();
    }
    if (tid == 0) g_Z[l] = red[0];
}

// ---------------- 4) fused row-normalize + column-sum (all 2B rows) ----------
__global__ __launch_bounds__(256) void fused_rc_kernel() {
    __shared__ float su[KPAD];
    __shared__ float sv[8];
    int tid = threadIdx.x, lane = tid & 31, wid = tid >> 5;
    int rbase = (int)blockIdx.x * RPB;
    int l = (rbase >= BB) ? 0 : 1;
    const float* W = g_W + (size_t)l * KPAD;
    float Z = g_Z[l];
    for (int i = tid; i < KK; i += 256) su[i] = Z / ((float)KK * W[i]);
    __syncthreads();

    float accx[6], accy[6];
#pragma unroll
    for (int i = 0; i < 6; i++) { accx[i] = 0.f; accy[i] = 0.f; }

    for (int j = 0; j < RPB / 8; j++) {
        const __nv_bfloat16* row = g_E + (size_t)(rbase + j * 8 + wid) * KK;
        float m = 0.f;
        for (int i = lane; i < KK / 8; i += 32) {
            uint4 raw = *(const uint4*)(row + i * 8);
            const __nv_bfloat162* h = (const __nv_bfloat162*)&raw;
            float4 u0 = *(const float4*)&su[i * 8];
            float4 u1 = *(const float4*)&su[i * 8 + 4];
            float2 e0 = __bfloat1622float2(h[0]);
            float2 e1 = __bfloat1622float2(h[1]);
            float2 e2 = __bfloat1622float2(h[2]);
            float2 e3 = __bfloat1622float2(h[3]);
            m += e0.x * u0.x + e0.y * u0.y + e1.x * u0.z + e1.y * u0.w
               + e2.x * u1.x + e2.y * u1.y + e3.x * u1.z + e3.y * u1.w;
        }
#pragma unroll
        for (int o = 16; o > 0; o >>= 1) m += __shfl_xor_sync(0xffffffffu, m, o);
        if (lane == 0) sv[wid] = Z / ((float)BB * m);
        __syncthreads();

#pragma unroll
        for (int rr = 0; rr < 8; rr++) {
            float vv = sv[rr];
            const __nv_bfloat16* row2 = g_E + (size_t)(rbase + j * 8 + rr) * KK;
#pragma unroll
            for (int i = 0; i < 6; i++) {
                int c = 2 * tid + 512 * i;
                if (c < KK) {
                    uint32_t raw = *(const uint32_t*)(row2 + c);
                    float2 e = __bfloat1622float2(*(__nv_bfloat162*)&raw);
                    accx[i] += vv * e.x;
                    accy[i] += vv * e.y;
                }
            }
        }
        __syncthreads();
    }
#pragma unroll
    for (int i = 0; i < 6; i++) {
        int c = 2 * tid + 512 * i;
        if (c < KK)
            *(float2*)&g_part2[(size_t)blockIdx.x * KPAD + c] = make_float2(accx[i], accy[i]);
    }
}

// ---------------- 5) final: both losses per row-pair, pred recovered from E --
// loss0: sim = E_k (u=ul0), pred from E_q;  loss1: swap.
__global__ __launch_bounds__(256) void final_pair_kernel() {
    __shared__ __nv_bfloat16 sEq[KK];
    __shared__ __nv_bfloat16 sEk[KK];
    __shared__ float red[32];
    int tid = threadIdx.x, lane = tid & 31, wid = tid >> 5;
    int r0 = (int)blockIdx.x * RFB;

    float4 uu0[6], uu1[6];
    const float4* ulp0 = (const float4*)(g_ul);
    const float4* ulp1 = (const float4*)(g_ul + KK);
#pragma unroll
    for (int i = 0; i < 6; i++) {
        int p2 = tid + 256 * i;
        bool in = (p2 < KK / 2);
        uu0[i] = in ? ulp0[p2] : make_float4(0.f, 0.f, 0.f, 0.f);
        uu1[i] = in ? ulp1[p2] : make_float4(0.f, 0.f, 0.f, 0.f);
    }
    const float M2 = C_EXP10;   // pred/T <= 10 => base2 exponent <= 14.427

    for (int j = 0; j < RFB; j++) {
        int rr = r0 + j;
        const uint4* pq = (const uint4*)(g_E + (size_t)rr * KK);
        const uint4* pk = (const uint4*)(g_E + (size_t)(BB + rr) * KK);
        for (int i = tid; i < KK / 8; i += 256) {
            ((uint4*)sEq)[i] = pq[i];
            ((uint4*)sEk)[i] = pk[i];
        }
        __syncthreads();

        // pass 1: Mb (both), lse-sum (both); stash lg2 values
        float2 lq[6], lk[6];
        float a0 = 0.f, a1 = 0.f, s0 = 0.f, s1 = 0.f;
#pragma unroll
        for (int i = 0; i < 6; i++) {
            int p2 = tid + 256 * i;
            if (p2 < KK / 2) {
                float2 eq = __bfloat1622float2(((const __nv_bfloat162*)sEq)[p2]);
                float2 ek = __bfloat1622float2(((const __nv_bfloat162*)sEk)[p2]);
                lq[i] = make_float2(lg2f(eq.x), lg2f(eq.y));
                lk[i] = make_float2(lg2f(ek.x), lg2f(ek.y));
                a0 += uu0[i].x * ek.x + uu0[i].z * ek.y;   // loss0 sim = Ek
                a1 += uu1[i].x * eq.x + uu1[i].z * eq.y;   // loss1 sim = Eq
                s0 += ex2f(fmaf(0.5f, lq[i].x, -M2)) + ex2f(fmaf(0.5f, lq[i].y, -M2));
                s1 += ex2f(fmaf(0.5f, lk[i].x, -M2)) + ex2f(fmaf(0.5f, lk[i].y, -M2));
            } else {
                lq[i] = make_float2(0.f, 0.f);
                lk[i] = make_float2(0.f, 0.f);
            }
        }
#pragma unroll
        for (int o = 16; o > 0; o >>= 1) {
            a0 += __shfl_xor_sync(0xffffffffu, a0, o);
            a1 += __shfl_xor_sync(0xffffffffu, a1, o);
            s0 += __shfl_xor_sync(0xffffffffu, s0, o);
            s1 += __shfl_xor_sync(0xffffffffu, s1, o);
        }
        if (lane == 0) { red[wid] = a0; red[8 + wid] = a1; red[16 + wid] = s0; red[24 + wid] = s1; }
        __syncthreads();
        float Mb0 = 0.f, Mb1 = 0.f, se0 = 0.f, se1 = 0.f;
#pragma unroll
        for (int w = 0; w < 8; w++) {
            Mb0 += red[w]; Mb1 += red[8 + w]; se0 += red[16 + w]; se1 += red[24 + w];
        }
        float lse0 = C_LN2 * (M2 + log2f(se0));
        float lse1 = C_LN2 * (M2 + log2f(se1));
        float logMb0 = logf(Mb0), logMb1 = logf(Mb1);

        // pass 2: KL for both losses (logp = 0.5*ln2*lg2(E_pred) - lse)
        float L0 = 0.f, L1 = 0.f;
#pragma unroll
        for (int i = 0; i < 6; i++) {
            int p2 = tid + 256 * i;
            if (p2 < KK / 2) {
                float2 eq = __bfloat1622float2(((const __nv_bfloat162*)sEq)[p2]);
                float2 ek = __bfloat1622float2(((const __nv_bfloat162*)sEk)[p2]);
                // loss0: code from Ek, pred from Eq
                float t0x = uu0[i].y + C_LN2 * lk[i].x - logMb0
                          - fmaf(0.5f * C_LN2, lq[i].x, -lse0);
                float t0y = uu0[i].w + C_LN2 * lk[i].y - logMb0
                          - fmaf(0.5f * C_LN2, lq[i].y, -lse0);
                L0 += uu0[i].x * ek.x * t0x + uu0[i].z * ek.y * t0y;
                // loss1: code from Eq, pred from Ek
                float t1x = uu1[i].y + C_LN2 * lq[i].x - logMb1
                          - fmaf(0.5f * C_LN2, lk[i].x, -lse1);
                float t1y = uu1[i].w + C_LN2 * lq[i].y - logMb1
                          - fmaf(0.5f * C_LN2, lk[i].y, -lse1);
                L1 += uu1[i].x * eq.x * t1x + uu1[i].z * eq.y * t1y;
            }
        }
#pragma unroll
        for (int o = 16; o > 0; o >>= 1) {
            L0 += __shfl_xor_sync(0xffffffffu, L0, o);
            L1 += __shfl_xor_sync(0xffffffffu, L1, o);
        }
        __syncthreads();
        if (lane == 0) { red[wid] = L0; red[8 + wid] = L1; }
        __syncthreads();
        if (tid == 0) {
            float Ls0 = 0.f, Ls1 = 0.f;
#pragma unroll
            for (int w = 0; w < 8; w++) { Ls0 += red[w]; Ls1 += red[8 + w]; }
            g_rowloss[rr] = Ls0 / Mb0 + Ls1 / Mb1;
        }
        __syncthreads();
    }
}

__global__ void loss_reduce_kernel(float* out) {
    __shared__ float red[1024];
    int tid = threadIdx.x;
    float a = 0.0f;
    for (int b = tid; b < BB; b += 1024) a += g_rowloss[b];
    red[tid] = a; __syncthreads();
    for (int s = 512; s > 0; s >>= 1) {
        if (tid < s) red[tid] += red[tid + s];
        __syncthreads();
    }
    if (tid == 0) out[0] = red[0] / (float)(2 * BB);
}

// ---------------- launch ------------------------------------------------------
extern "C" void kernel_launch(void* const* d_in, const int* in_sizes, int n_in,
                              void* d_out, int out_size) {
    const float* q = (const float*)d_in[0];
    const float* k = (const float*)d_in[1];
    const float* c = (const float*)d_in[2];

    cudaFuncSetAttribute(gemm_mma_kernel, cudaFuncAttributeMaxDynamicSharedMemorySize,
                         GSTAGE * STAGE_BYTES);

    l2norm_all_kernel<<<(2 * BB + KPAD) / 8, 256>>>(q, k, c);
    gemm_mma_kernel<<<(2 * BB / 128) * (KPAD / 128), 256, GSTAGE * STAGE_BYTES>>>();

    reduce_w_epi_kernel<<<dim3(6, 2), dim3(128, 4)>>>();       // W1
    zreduce_kernel<<<2, 1024>>>();                             // Z
    fused_rc_kernel<<<NFB2, 256>>>();                          // v1; W2 partials
    reduce_w_fused_kernel<<<dim3(6, 2), dim3(128, 8)>>>(0);    // W2
    fused_rc_kernel<<<NFB2, 256>>>();                          // v2; W3 partials
    reduce_w_fused_kernel<<<dim3(6, 2), dim3(128, 8)>>>(1);    // W3 + u3
    final_pair_kernel<<<BB / RFB, 256>>>();                    // both losses per row
    loss_reduce_kernel<<<1, 1024>>>((float*)d_out);
}

// round 10
// speedup vs baseline: 4.1928x; 1.0281x over previous
#include <cuda_runtime.h>
#include <cuda_bf16.h>
#include <cstdint>

#define BB 16384
#define DD 256
#define KK 3000
#define KPAD 3072
#define NFB2 1024        // fused row/col blocks over ALL 2B rows
#define RPB 32           // rows per fused block
#define RFB 8            // row-pairs per final block

#define C_EXP20 28.853900817779268f   // 20/ln2
#define C_EXP10 14.426950408889634f   // 10/ln2
#define C_LN2   0.6931471805599453f

// ---------------- device scratch -------------------------------------------
__device__ __align__(16) __nv_bfloat16 g_A2[(size_t)2 * BB * DD];
__device__ __align__(16) __nv_bfloat16 g_B2[(size_t)KPAD * DD];
__device__ __align__(16) __nv_bfloat16 g_E[(size_t)2 * BB * KK];  // exp(sim/eps) bf16
__device__ float g_partW[(size_t)256 * KPAD];    // per-GEMM-mtile col partials of E
__device__ float g_part2[(size_t)NFB2 * KPAD];   // fused-pass col partials
__device__ float g_W[2 * KPAD];
__device__ float2 g_ul[2 * KK];                  // (u, log u) per loss
__device__ float g_rowloss[BB];

// ---------------- helpers ----------------------------------------------------
static __device__ __forceinline__ float ex2f(float x) {
    float y; asm("ex2.approx.ftz.f32 %0, %1;" : "=f"(y) : "f"(x)); return y;
}
static __device__ __forceinline__ float lg2f(float x) {
    float y; asm("lg2.approx.ftz.f32 %0, %1;" : "=f"(y) : "f"(x)); return y;
}
static __device__ __forceinline__ uint32_t s2u(const void* p) {
    uint32_t a;
    asm("{ .reg .u64 t; cvta.to.shared.u64 t, %1; cvt.u32.u64 %0, t; }" : "=r"(a) : "l"(p));
    return a;
}

#define LDSM4(r, a)                                                             \
    asm volatile("ldmatrix.sync.aligned.m8n8.x4.shared.b16 {%0,%1,%2,%3}, [%4];" \
                 : "=r"((r)[0]), "=r"((r)[1]), "=r"((r)[2]), "=r"((r)[3]) : "r"(a))

#define MMA16816(d, a, b)                                                       \
    asm volatile(                                                               \
        "mma.sync.aligned.m16n8k16.row.col.f32.bf16.bf16.f32 "                  \
        "{%0,%1,%2,%3}, {%4,%5,%6,%7}, {%8,%9}, {%0,%1,%2,%3};"                 \
        : "+f"((d)[0]), "+f"((d)[1]), "+f"((d)[2]), "+f"((d)[3])                \
        : "r"((a)[0]), "r"((a)[1]), "r"((a)[2]), "r"((a)[3]),                   \
          "r"((b)[0]), "r"((b)[1]))

#define CPASYNC16(dst, src) \
    asm volatile("cp.async.cg.shared.global [%0], [%1], 16;" :: "r"(dst), "l"(src))

// ---------------- 1) L2 normalize (q,k,c) + pad, one launch ------------------
__global__ void l2norm_all_kernel(const float* __restrict__ q,
                                  const float* __restrict__ k,
                                  const float* __restrict__ c) {
    int row  = blockIdx.x * 8 + (threadIdx.x >> 5);
    int lane = threadIdx.x & 31;
    if (row >= 2 * BB + KPAD) return;

    const float* src;
    __nv_bfloat16* dst;
    if (row < BB)            { src = q + (size_t)row * DD;            dst = g_A2 + (size_t)row * DD; }
    else if (row < 2 * BB)   { src = k + (size_t)(row - BB) * DD;     dst = g_A2 + (size_t)row * DD; }
    else if (row < 2 * BB + KK) { src = c + (size_t)(row - 2 * BB) * DD; dst = g_B2 + (size_t)(row - 2 * BB) * DD; }
    else {
        dst = g_B2 + (size_t)(row - 2 * BB) * DD;
#pragma unroll
        for (int i = 0; i < 8; i++) dst[lane + 32 * i] = __float2bfloat16(0.0f);
        return;
    }
    float v[8]; float s = 0.0f;
#pragma unroll
    for (int i = 0; i < 8; i++) { v[i] = src[lane + 32 * i]; s += v[i] * v[i]; }
#pragma unroll
    for (int o = 16; o > 0; o >>= 1) s += __shfl_xor_sync(0xffffffffu, s, o);
    float inv = 1.0f / fmaxf(sqrtf(s), 1e-12f);
#pragma unroll
    for (int i = 0; i < 8; i++) dst[lane + 32 * i] = __float2bfloat16(v[i] * inv);
}

// ---------------- 2) GEMM 128x256 tile + fused epilogue (E, W1-partials) -----
#define GSTAGE 3
#define STAGE_BYTES 49152   // A 16KB + B 32KB
#define NIT (DD / 64)       // 4

__global__ __launch_bounds__(256) void gemm_mma_kernel() {
    extern __shared__ char smem[];
    const uint32_t sb = s2u(smem);
    const int tid = threadIdx.x;
    const int lane = tid & 31;
    const int wid = tid >> 5;
    const int wm = wid >> 2;          // 0..1  (64-row group)
    const int wn = wid & 3;           // 0..3  (64-col group)

    const int nTilesN = KPAD / 256;   // 12
    const int mBase = (int)(blockIdx.x / nTilesN) * 128;
    const int nBase = (int)(blockIdx.x % nTilesN) * 256;

    const __nv_bfloat16* gA = g_A2 + (size_t)mBase * DD;
    const __nv_bfloat16* gB = g_B2 + (size_t)nBase * DD;

    float acc[4][8][4] = {};

    auto load_stage = [&](int s, int kIter) {
        uint32_t so = sb + (uint32_t)s * STAGE_BYTES;
        int k0 = kIter * 64;
#pragma unroll
        for (int i = 0; i < 12; i++) {
            int q = tid + i * 256;          // 0..3071 (A: 0..1023, B: 1024..3071)
            int isB = (q >= 1024);
            int idx = isB ? (q - 1024) : q;
            int row = idx >> 3;
            int c = idx & 7;
            uint32_t dst = so + (isB ? 16384 : 0) + row * 128 + ((c ^ (row & 7)) << 4);
            const __nv_bfloat16* src = isB ? (gB + (size_t)row * DD + k0 + c * 8)
                                           : (gA + (size_t)row * DD + k0 + c * 8);
            CPASYNC16(dst, src);
        }
        asm volatile("cp.async.commit_group;" ::: "memory");
    };

    load_stage(0, 0);
    load_stage(1, 1);

    for (int it = 0; it < NIT; it++) {
        if (it + 2 < NIT) asm volatile("cp.async.wait_group 1;" ::: "memory");
        else              asm volatile("cp.async.wait_group 0;" ::: "memory");
        __syncthreads();
        if (it + 2 < NIT) load_stage((it + 2) % GSTAGE, it + 2);

        uint32_t aB = sb + (uint32_t)(it % GSTAGE) * STAGE_BYTES;
        uint32_t bB = aB + 16384;
#pragma unroll
        for (int ks = 0; ks < 4; ks++) {
            uint32_t a[4][4], b[8][2];
            int cch = ks * 2 + (lane >> 4);
#pragma unroll
            for (int mi = 0; mi < 4; mi++) {
                int row = wm * 64 + mi * 16 + (lane & 15);
                uint32_t addr = aB + row * 128 + ((cch ^ (row & 7)) << 4);
                LDSM4(a[mi], addr);
            }
#pragma unroll
            for (int nj = 0; nj < 4; nj++) {
                int row = wn * 64 + nj * 16 + (lane & 15);
                uint32_t addr = bB + row * 128 + ((cch ^ (row & 7)) << 4);
                uint32_t r4[4];
                LDSM4(r4, addr);
                b[nj * 2][0]     = r4[0]; b[nj * 2][1]     = r4[2];
                b[nj * 2 + 1][0] = r4[1]; b[nj * 2 + 1][1] = r4[3];
            }
#pragma unroll
            for (int mi = 0; mi < 4; mi++)
#pragma unroll
                for (int ni = 0; ni < 8; ni++)
                    MMA16816(acc[mi][ni], a[mi], b[ni]);
        }
        __syncthreads();
    }

    // fused epilogue: E bf16 + per-tile column sums of E
    float* cs = (float*)smem;   // [2][256]
    float cp0[8], cp1[8];
#pragma unroll
    for (int ni = 0; ni < 8; ni++) { cp0[ni] = 0.f; cp1[ni] = 0.f; }

#pragma unroll
    for (int ni = 0; ni < 8; ni++) {
        int gn = nBase + wn * 64 + ni * 8 + (lane & 3) * 2;
        bool ok = (gn < KK);
#pragma unroll
        for (int mi = 0; mi < 4; mi++) {
            int gm = mBase + wm * 64 + mi * 16 + (lane >> 2);
            float e0 = ex2f(acc[mi][ni][0] * C_EXP20), e1 = ex2f(acc[mi][ni][1] * C_EXP20);
            float e2 = ex2f(acc[mi][ni][2] * C_EXP20), e3 = ex2f(acc[mi][ni][3] * C_EXP20);
            if (ok) {
                __nv_bfloat162 eh0 = __floats2bfloat162_rn(e0, e1);
                __nv_bfloat162 eh1 = __floats2bfloat162_rn(e2, e3);
                *(uint32_t*)&g_E[(size_t)gm * KK + gn]       = *(uint32_t*)&eh0;
                *(uint32_t*)&g_E[(size_t)(gm + 8) * KK + gn] = *(uint32_t*)&eh1;
                cp0[ni] += e0 + e2;
                cp1[ni] += e1 + e3;
            }
        }
    }
#pragma unroll
    for (int ni = 0; ni < 8; ni++) {
#pragma unroll
        for (int o = 4; o < 32; o <<= 1) {
            cp0[ni] += __shfl_xor_sync(0xffffffffu, cp0[ni], o);
            cp1[ni] += __shfl_xor_sync(0xffffffffu, cp1[ni], o);
        }
        if (lane < 4) {
            cs[wm * 256 + wn * 64 + ni * 8 + lane * 2]     = cp0[ni];
            cs[wm * 256 + wn * 64 + ni * 8 + lane * 2 + 1] = cp1[ni];
        }
    }
    __syncthreads();
    {
        int mtile = (int)(blockIdx.x / nTilesN);
        g_partW[(size_t)mtile * KPAD + nBase + tid] = cs[tid] + cs[256 + tid];
    }
}

// ---------------- 3) slab reductions -----------------------------------------
__global__ void reduce_w_epi_kernel() {   // grid (6,2), block (128,4)
    int l = blockIdx.y;
    int halfStart = (l == 0) ? 128 : 0;
    int tx = threadIdx.x, ty = threadIdx.y;
    int k4 = (blockIdx.x * 128 + tx) * 4;
    __shared__ float4 sm[4][128];
    float4 s = make_float4(0.f, 0.f, 0.f, 0.f);
    if (k4 < KK) {
        const float* base = g_partW + (size_t)(halfStart + ty * 32) * KPAD + k4;
#pragma unroll 8
        for (int i = 0; i < 32; i++) {
            float4 p = *(const float4*)(base + (size_t)i * KPAD);
            s.x += p.x; s.y += p.y; s.z += p.z; s.w += p.w;
        }
    }
    sm[ty][tx] = s;
    __syncthreads();
    if (ty == 0 && k4 < KK) {
#pragma unroll
        for (int w = 1; w < 4; w++) {
            float4 p = sm[w][tx];
            s.x += p.x; s.y += p.y; s.z += p.z; s.w += p.w;
        }
        *(float4*)&g_W[l * KPAD + k4] = s;
    }
}

__global__ void reduce_w_fused_kernel(int writeU) {   // grid (6,2), block (128,8)
    int l = blockIdx.y;
    int slabStart = (l == 0) ? 512 : 0;
    int tx = threadIdx.x, ty = threadIdx.y;
    int k4 = (blockIdx.x * 128 + tx) * 4;
    __shared__ float4 sm[8][128];
    float4 s = make_float4(0.f, 0.f, 0.f, 0.f);
    if (k4 < KK) {
        const float* base = g_part2 + (size_t)(slabStart + ty * 64) * KPAD + k4;
#pragma unroll 8
        for (int i = 0; i < 64; i++) {
            float4 p = *(const float4*)(base + (size_t)i * KPAD);
            s.x += p.x; s.y += p.y; s.z += p.z; s.w += p.w;
        }
    }
    sm[ty][tx] = s;
    __syncthreads();
    if (ty == 0 && k4 < KK) {
#pragma unroll
        for (int w = 1; w < 8; w++) {
            float4 p = sm[w][tx];
            s.x += p.x; s.y += p.y; s.z += p.z; s.w += p.w;
        }
        *(float4*)&g_W[l * KPAD + k4] = s;
        if (writeU) {
            float u0 = 1.0f / ((float)KK * s.x), u1 = 1.0f / ((float)KK * s.y);
            float u2 = 1.0f / ((float)KK * s.z), u3 = 1.0f / ((float)KK * s.w);
            g_ul[l * KK + k4]     = make_float2(u0, logf(u0));
            g_ul[l * KK + k4 + 1] = make_float2(u1, logf(u1));
            g_ul[l * KK + k4 + 2] = make_float2(u2, logf(u2));
            g_ul[l * KK + k4 + 3] = make_float2(u3, logf(u3));
        }
    }
}

// ---------------- 4) fused row-normalize + column-sum (Z == 1) ---------------
__global__ __launch_bounds__(256) void fused_rc_kernel() {
    __shared__ float su[KPAD];
    __shared__ float sv[8];
    int tid = threadIdx.x, lane = tid & 31, wid = tid >> 5;
    int rbase = (int)blockIdx.x * RPB;
    int l = (rbase >= BB) ? 0 : 1;
    const float* W = g_W + (size_t)l * KPAD;
    for (int i = tid; i < KK; i += 256) su[i] = 1.0f / ((float)KK * W[i]);
    __syncthreads();

    float accx[6], accy[6];
#pragma unroll
    for (int i = 0; i < 6; i++) { accx[i] = 0.f; accy[i] = 0.f; }

    for (int j = 0; j < RPB / 8; j++) {
        const __nv_bfloat16* row = g_E + (size_t)(rbase + j * 8 + wid) * KK;
        float m = 0.f;
        for (int i = lane; i < KK / 8; i += 32) {
            uint4 raw = *(const uint4*)(row + i * 8);
            const __nv_bfloat162* h = (const __nv_bfloat162*)&raw;
            float4 u0 = *(const float4*)&su[i * 8];
            float4 u1 = *(const float4*)&su[i * 8 + 4];
            float2 e0 = __bfloat1622float2(h[0]);
            float2 e1 = __bfloat1622float2(h[1]);
            float2 e2 = __bfloat1622float2(h[2]);
            float2 e3 = __bfloat1622float2(h[3]);
            m += e0.x * u0.x + e0.y * u0.y + e1.x * u0.z + e1.y * u0.w
               + e2.x * u1.x + e2.y * u1.y + e3.x * u1.z + e3.y * u1.w;
        }
#pragma unroll
        for (int o = 16; o > 0; o >>= 1) m += __shfl_xor_sync(0xffffffffu, m, o);
        if (lane == 0) sv[wid] = 1.0f / ((float)BB * m);
        __syncthreads();

#pragma unroll
        for (int rr = 0; rr < 8; rr++) {
            float vv = sv[rr];
            const __nv_bfloat16* row2 = g_E + (size_t)(rbase + j * 8 + rr) * KK;
#pragma unroll
            for (int i = 0; i < 6; i++) {
                int c = 2 * tid + 512 * i;
                if (c < KK) {
                    uint32_t raw = *(const uint32_t*)(row2 + c);
                    float2 e = __bfloat1622float2(*(__nv_bfloat162*)&raw);
                    accx[i] += vv * e.x;
                    accy[i] += vv * e.y;
                }
            }
        }
        __syncthreads();
    }
#pragma unroll
    for (int i = 0; i < 6; i++) {
        int c = 2 * tid + 512 * i;
        if (c < KK)
            *(float2*)&g_part2[(size_t)blockIdx.x * KPAD + c] = make_float2(accx[i], accy[i]);
    }
}

// ---------------- 5) final: both losses per row-pair, pred recovered from E --
__global__ __launch_bounds__(256) void final_pair_kernel() {
    __shared__ __nv_bfloat16 sEq[KK];
    __shared__ __nv_bfloat16 sEk[KK];
    __shared__ float red[32];
    int tid = threadIdx.x, lane = tid & 31, wid = tid >> 5;
    int r0 = (int)blockIdx.x * RFB;

    float4 uu0[6], uu1[6];
    const float4* ulp0 = (const float4*)(g_ul);
    const float4* ulp1 = (const float4*)(g_ul + KK);
#pragma unroll
    for (int i = 0; i < 6; i++) {
        int p2 = tid + 256 * i;
        bool in = (p2 < KK / 2);
        uu0[i] = in ? ulp0[p2] : make_float4(0.f, 0.f, 0.f, 0.f);
        uu1[i] = in ? ulp1[p2] : make_float4(0.f, 0.f, 0.f, 0.f);
    }
    const float M2 = C_EXP10;

    for (int j = 0; j < RFB; j++) {
        int rr = r0 + j;
        const uint4* pq = (const uint4*)(g_E + (size_t)rr * KK);
        const uint4* pk = (const uint4*)(g_E + (size_t)(BB + rr) * KK);
        for (int i = tid; i < KK / 8; i += 256) {
            ((uint4*)sEq)[i] = pq[i];
            ((uint4*)sEk)[i] = pk[i];
        }
        __syncthreads();

        float2 lq[6], lk[6];
        float a0 = 0.f, a1 = 0.f, s0 = 0.f, s1 = 0.f;
#pragma unroll
        for (int i = 0; i < 6; i++) {
            int p2 = tid + 256 * i;
            if (p2 < KK / 2) {
                float2 eq = __bfloat1622float2(((const __nv_bfloat162*)sEq)[p2]);
                float2 ek = __bfloat1622float2(((const __nv_bfloat162*)sEk)[p2]);
                lq[i] = make_float2(lg2f(eq.x), lg2f(eq.y));
                lk[i] = make_float2(lg2f(ek.x), lg2f(ek.y));
                a0 += uu0[i].x * ek.x + uu0[i].z * ek.y;
                a1 += uu1[i].x * eq.x + uu1[i].z * eq.y;
                s0 += ex2f(fmaf(0.5f, lq[i].x, -M2)) + ex2f(fmaf(0.5f, lq[i].y, -M2));
                s1 += ex2f(fmaf(0.5f, lk[i].x, -M2)) + ex2f(fmaf(0.5f, lk[i].y, -M2));
            } else {
                lq[i] = make_float2(0.f, 0.f);
                lk[i] = make_float2(0.f, 0.f);
            }
        }
#pragma unroll
        for (int o = 16; o > 0; o >>= 1) {
            a0 += __shfl_xor_sync(0xffffffffu, a0, o);
            a1 += __shfl_xor_sync(0xffffffffu, a1, o);
            s0 += __shfl_xor_sync(0xffffffffu, s0, o);
            s1 += __shfl_xor_sync(0xffffffffu, s1, o);
        }
        if (lane == 0) { red[wid] = a0; red[8 + wid] = a1; red[16 + wid] = s0; red[24 + wid] = s1; }
        __syncthreads();
        float Mb0 = 0.f, Mb1 = 0.f, se0 = 0.f, se1 = 0.f;
#pragma unroll
        for (int w = 0; w < 8; w++) {
            Mb0 += red[w]; Mb1 += red[8 + w]; se0 += red[16 + w]; se1 += red[24 + w];
        }
        float lse0 = C_LN2 * (M2 + log2f(se0));
        float lse1 = C_LN2 * (M2 + log2f(se1));
        float logMb0 = logf(Mb0), logMb1 = logf(Mb1);

        float L0 = 0.f, L1 = 0.f;
#pragma unroll
        for (int i = 0; i < 6; i++) {
            int p2 = tid + 256 * i;
            if (p2 < KK / 2) {
                float2 eq = __bfloat1622float2(((const __nv_bfloat162*)sEq)[p2]);
                float2 ek = __bfloat1622float2(((const __nv_bfloat162*)sEk)[p2]);
                float t0x = uu0[i].y + C_LN2 * lk[i].x - logMb0
                          - fmaf(0.5f * C_LN2, lq[i].x, -lse0);
                float t0y = uu0[i].w + C_LN2 * lk[i].y - logMb0
                          - fmaf(0.5f * C_LN2, lq[i].y, -lse0);
                L0 += uu0[i].x * ek.x * t0x + uu0[i].z * ek.y * t0y;
                float t1x = uu1[i].y + C_LN2 * lq[i].x - logMb1
                          - fmaf(0.5f * C_LN2, lk[i].x, -lse1);
                float t1y = uu1[i].w + C_LN2 * lq[i].y - logMb1
                          - fmaf(0.5f * C_LN2, lk[i].y, -lse1);
                L1 += uu1[i].x * eq.x * t1x + uu1[i].z * eq.y * t1y;
            }
        }
#pragma unroll
        for (int o = 16; o > 0; o >>= 1) {
            L0 += __shfl_xor_sync(0xffffffffu, L0, o);
            L1 += __shfl_xor_sync(0xffffffffu, L1, o);
        }
        __syncthreads();
        if (lane == 0) { red[wid] = L0; red[8 + wid] = L1; }
        __syncthreads();
        if (tid == 0) {
            float Ls0 = 0.f, Ls1 = 0.f;
#pragma unroll
            for (int w = 0; w < 8; w++) { Ls0 += red[w]; Ls1 += red[8 + w]; }
            g_rowloss[rr] = Ls0 / Mb0 + Ls1 / Mb1;
        }
        __syncthreads();
    }
}

__global__ void loss_reduce_kernel(float* out) {
    __shared__ float red[1024];
    int tid = threadIdx.x;
    float a = 0.0f;
    for (int b = tid; b < BB; b += 1024) a += g_rowloss[b];
    red[tid] = a; __syncthreads();
    for (int s = 512; s > 0; s >>= 1) {
        if (tid < s) red[tid] += red[tid + s];
        __syncthreads();
    }
    if (tid == 0) out[0] = red[0] / (float)(2 * BB);
}

// ---------------- launch ------------------------------------------------------
extern "C" void kernel_launch(void* const* d_in, const int* in_sizes, int n_in,
                              void* d_out, int out_size) {
    const float* q = (const float*)d_in[0];
    const float* k = (const float*)d_in[1];
    const float* c = (const float*)d_in[2];

    cudaFuncSetAttribute(gemm_mma_kernel, cudaFuncAttributeMaxDynamicSharedMemorySize,
                         GSTAGE * STAGE_BYTES);

    l2norm_all_kernel<<<(2 * BB + KPAD) / 8, 256>>>(q, k, c);
    gemm_mma_kernel<<<(2 * BB / 128) * (KPAD / 256), 256, GSTAGE * STAGE_BYTES>>>();

    reduce_w_epi_kernel<<<dim3(6, 2), dim3(128, 4)>>>();       // W1
    fused_rc_kernel<<<NFB2, 256>>>();                          // v1; W2 partials
    reduce_w_fused_kernel<<<dim3(6, 2), dim3(128, 8)>>>(0);    // W2
    fused_rc_kernel<<<NFB2, 256>>>();                          // v2; W3 partials
    reduce_w_fused_kernel<<<dim3(6, 2), dim3(128, 8)>>>(1);    // W3 + u3
    final_pair_kernel<<<BB / RFB, 256>>>();                    // both losses per row
    loss_reduce_kernel<<<1, 1024>>>((float*)d_out);
}